// round 5
// baseline (speedup 1.0000x reference)
#include <cuda_runtime.h>
#include <cstdio>

// ---------------------------------------------------------------------------
// Problem constants
// ---------------------------------------------------------------------------
#define NPIX 65536              // 256*256
#define HW 256

// ---------------------------------------------------------------------------
// Scratch (static __device__ arrays; no allocations allowed)
// ---------------------------------------------------------------------------
__device__ float g_Wx1[2 * 121 * NPIX];
__device__ float g_Wx2[2 * 121 * NPIX];
__device__ float g_z  [2 * 121 * NPIX];
__device__ float g_tA [2 * 121 * NPIX];
__device__ float g_tB [2 * 121 * NPIX];
__device__ float g_cat[2 * 122 * NPIX];
__device__ float g_ln [2 * 122 * NPIX];
__device__ float g_out[2 * 122 * NPIX];
__device__ float g_h  [2 * 732 * NPIX];
__device__ float g_h2 [2 * 732 * NPIX];
__device__ float g_wT2[121 * 121 * 121];
__device__ float g_wT1[121 * 121];
__device__ float g_sey[2 * 122];
__device__ float g_se [2 * 122];
__device__ double g_loss;

__device__ __forceinline__ int refl(int i) {
    i = (i < 0) ? -i : i;
    return (i < HW) ? i : (2 * HW - 2 - i);
}

// ---------------------------------------------------------------------------
// Weight prep: wT = rot180(transpose(w))  ->  wT[o][i][tap] = w[i][o][120-tap]
// ---------------------------------------------------------------------------
__global__ void prep_w_kern(const float* __restrict__ w1, const float* __restrict__ w2)
{
    int i0 = blockIdx.x * 256 + threadIdx.x;
    if (i0 < 121 * 121) {
        int ci = i0 / 121, tap = i0 % 121;
        g_wT1[ci * 121 + tap] = w1[ci * 121 + (120 - tap)];
    }
    for (int t = i0; t < 121 * 121 * 121; t += gridDim.x * 256) {
        int co  = t / 14641;
        int rem = t - co * 14641;
        int ci  = rem / 121, tap = rem - ci * 121;
        g_wT2[(co * 121 + ci) * 121 + tap] = w2[(ci * 121 + co) * 121 + (120 - tap)];
    }
}

// ---------------------------------------------------------------------------
// Generic KSxKS conv (cross-correlation), 32x32 output tile, 8 co / block.
// REFLECT: reflect padding (pad=KS/2) ; else zero pad.
// chscale: optional per-(b,ci) input scale (SE). CLIP: clamp [0,10] after bias.
// ---------------------------------------------------------------------------
template<int KS, bool REFLECT, bool CLIP>
__global__ void __launch_bounds__(256) convK_kern(
    const float* __restrict__ in, const float* __restrict__ wbuf,
    const float* __restrict__ bias, const float* __restrict__ chscale,
    float* __restrict__ out, int Cin, int Cout, float outscale)
{
    constexpr int PAD = KS / 2;
    constexpr int IN  = 32 + KS - 1;
    constexpr int STR = IN + 1;          // odd stride -> conflict-free 2-row access
    constexpr int KK  = KS * KS;
    // s_w8 MUST be 16B-aligned: it is read via float4 (LDS.128 traps on
    // misaligned addresses). Each tap group is 8 floats = 32B, so alignment
    // of the base is sufficient.
    __shared__ __align__(16) float s_w8[KK * 8];   // [tap][8 co]
    __shared__ float s_in[IN * STR];

    const int nCoG = (Cout + 7) >> 3;
    const int b    = blockIdx.z / nCoG;
    const int cog  = blockIdx.z % nCoG;
    const int by = blockIdx.y, bx = blockIdx.x;
    const int tid = threadIdx.x;
    const int ty = tid >> 4, tx = tid & 15;
    const int r0 = ty * 2, c0 = tx * 2;

    float acc[4][8];
#pragma unroll
    for (int p = 0; p < 4; ++p)
#pragma unroll
        for (int j = 0; j < 8; ++j) acc[p][j] = 0.f;

    const size_t inBase  = (size_t)b * Cin * NPIX;
    const int    co0     = cog * 8;
    const size_t wstride = (size_t)Cin * KK;

    for (int ci = 0; ci < Cin; ++ci) {
        const float* ip = in + inBase + (size_t)ci * NPIX;
        float sc = 1.f;
        if (chscale) sc = chscale[b * Cin + ci];
        for (int idx = tid; idx < IN * IN; idx += 256) {
            int row = idx / IN, col = idx - row * IN;
            int gy = by * 32 + row - PAD;
            int gx = bx * 32 + col - PAD;
            float v;
            if (REFLECT) {
                v = ip[refl(gy) * HW + refl(gx)];
            } else {
                v = (gy >= 0 && gy < HW && gx >= 0 && gx < HW) ? ip[gy * HW + gx] : 0.f;
            }
            s_in[row * STR + col] = v * sc;
        }
        {
            const float* wci = wbuf + (size_t)ci * KK;
            for (int t = tid; t < KK * 8; t += 256) {
                int tap = t >> 3, j = t & 7;
                int co  = co0 + j;
                // branch-free: read a valid address, zero-select OOB lanes
                int cosafe = (co < Cout) ? co : (Cout - 1);
                float wv = wci[(size_t)cosafe * wstride + tap];
                s_w8[t] = (co < Cout) ? wv : 0.f;
            }
        }
        __syncthreads();
#pragma unroll 1
        for (int r = 0; r < KS; ++r) {
            const float* p0 = &s_in[(r0 + r) * STR + c0];
            const float* p1 = p0 + STR;
#pragma unroll
            for (int s = 0; s < KS; ++s) {
                const float4* wp = (const float4*)&s_w8[(r * KS + s) * 8];
                float4 wa = wp[0], wb = wp[1];
                float v00 = p0[s], v01 = p0[s + 1];
                float v10 = p1[s], v11 = p1[s + 1];
                acc[0][0] += wa.x * v00; acc[0][1] += wa.y * v00; acc[0][2] += wa.z * v00; acc[0][3] += wa.w * v00;
                acc[0][4] += wb.x * v00; acc[0][5] += wb.y * v00; acc[0][6] += wb.z * v00; acc[0][7] += wb.w * v00;
                acc[1][0] += wa.x * v01; acc[1][1] += wa.y * v01; acc[1][2] += wa.z * v01; acc[1][3] += wa.w * v01;
                acc[1][4] += wb.x * v01; acc[1][5] += wb.y * v01; acc[1][6] += wb.z * v01; acc[1][7] += wb.w * v01;
                acc[2][0] += wa.x * v10; acc[2][1] += wa.y * v10; acc[2][2] += wa.z * v10; acc[2][3] += wa.w * v10;
                acc[2][4] += wb.x * v10; acc[2][5] += wb.y * v10; acc[2][6] += wb.z * v10; acc[2][7] += wb.w * v10;
                acc[3][0] += wa.x * v11; acc[3][1] += wa.y * v11; acc[3][2] += wa.z * v11; acc[3][3] += wa.w * v11;
                acc[3][4] += wb.x * v11; acc[3][5] += wb.y * v11; acc[3][6] += wb.z * v11; acc[3][7] += wb.w * v11;
            }
        }
        __syncthreads();
    }

    const int oy = by * 32 + r0, ox = bx * 32 + c0;
    const size_t outBase = (size_t)b * Cout * NPIX;
#pragma unroll
    for (int j = 0; j < 8; ++j) {
        int co = co0 + j;
        if (co >= Cout) break;
        float bv = bias ? bias[co] : 0.f;
        float* op = out + outBase + (size_t)co * NPIX;
        float r00 = acc[0][j] * outscale + bv;
        float r01 = acc[1][j] * outscale + bv;
        float r10 = acc[2][j] * outscale + bv;
        float r11 = acc[3][j] * outscale + bv;
        if (CLIP) {
            r00 = fminf(fmaxf(r00, 0.f), 10.f);
            r01 = fminf(fmaxf(r01, 0.f), 10.f);
            r10 = fminf(fmaxf(r10, 0.f), 10.f);
            r11 = fminf(fmaxf(r11, 0.f), 10.f);
        }
        op[oy * HW + ox]           = r00;
        op[oy * HW + ox + 1]       = r01;
        op[(oy + 1) * HW + ox]     = r10;
        op[(oy + 1) * HW + ox + 1] = r11;
    }
}

// ---------------------------------------------------------------------------
// 1x1 conv (channel GEMM). 256 px/block, 16 co/block. Optional residual add.
// ---------------------------------------------------------------------------
template<bool RESID>
__global__ void __launch_bounds__(256) conv1x1_kern(
    const float* __restrict__ x, const float* __restrict__ w,
    const float* __restrict__ resid, float* __restrict__ out,
    int Cin, int Cout)
{
    __shared__ float4 s_w[244 * 4];
    const int b   = blockIdx.z;
    const int co0 = blockIdx.y * 16;
    const int px  = blockIdx.x * 256 + threadIdx.x;
    for (int t = threadIdx.x; t < Cin * 4; t += 256) {
        int ci = t >> 2, g = t & 3;
        int co = co0 + g * 4;
        float4 v;
        v.x = (co + 0 < Cout) ? w[(size_t)(co + 0) * Cin + ci] : 0.f;
        v.y = (co + 1 < Cout) ? w[(size_t)(co + 1) * Cin + ci] : 0.f;
        v.z = (co + 2 < Cout) ? w[(size_t)(co + 2) * Cin + ci] : 0.f;
        v.w = (co + 3 < Cout) ? w[(size_t)(co + 3) * Cin + ci] : 0.f;
        s_w[t] = v;
    }
    __syncthreads();
    float acc[16];
#pragma unroll
    for (int j = 0; j < 16; ++j) acc[j] = 0.f;
    const float* xp = x + (size_t)b * Cin * NPIX + px;
#pragma unroll 2
    for (int ci = 0; ci < Cin; ++ci) {
        float xv = xp[(size_t)ci * NPIX];
#pragma unroll
        for (int g = 0; g < 4; ++g) {
            float4 w4 = s_w[ci * 4 + g];
            acc[g * 4 + 0] += w4.x * xv;
            acc[g * 4 + 1] += w4.y * xv;
            acc[g * 4 + 2] += w4.z * xv;
            acc[g * 4 + 3] += w4.w * xv;
        }
    }
    const size_t ob = (size_t)b * Cout * NPIX + px;
#pragma unroll
    for (int j = 0; j < 16; ++j) {
        int co = co0 + j;
        if (co < Cout) {
            float v = acc[j];
            if (RESID) v += resid[ob + (size_t)co * NPIX];
            out[ob + (size_t)co * NPIX] = v;
        }
    }
}

// ---------------------------------------------------------------------------
// LayerNorm over 122 channels of concat([input, Wx]) per pixel.
// Writes both cat (for residual) and ln.
// ---------------------------------------------------------------------------
__global__ void ln_cat_kern(const float* __restrict__ in0, const float* __restrict__ wx,
                            const float* __restrict__ gw, const float* __restrict__ gb)
{
    int t = blockIdx.x * 256 + threadIdx.x;
    if (t >= 2 * NPIX) return;
    int b = t >> 16, p = t & (NPIX - 1);
    float x0 = in0[t];
    const float* wp = wx + (size_t)b * 121 * NPIX + p;
    float sum = x0, ss = x0 * x0;
    for (int c = 0; c < 121; ++c) {
        float v = wp[(size_t)c * NPIX];
        sum += v; ss += v * v;
    }
    float mu  = sum * (1.f / 122.f);
    float var = ss * (1.f / 122.f) - mu * mu;
    float rs  = rsqrtf(var + 1e-5f);
    size_t base = (size_t)b * 122 * NPIX + p;
    g_cat[base] = x0;
    g_ln[base]  = (x0 - mu) * rs * gw[0] + gb[0];
    for (int c = 0; c < 121; ++c) {
        float v = wp[(size_t)c * NPIX];
        g_cat[base + (size_t)(c + 1) * NPIX] = v;
        g_ln[base + (size_t)(c + 1) * NPIX]  = (v - mu) * rs * gw[c + 1] + gb[c + 1];
    }
}

// ---------------------------------------------------------------------------
// Depthwise 3x3, zero pad, 732 channels: g_h -> g_h2
// ---------------------------------------------------------------------------
__global__ void dwconv_kern(const float* __restrict__ w)
{
    int c = blockIdx.y, b = blockIdx.z;
    int p = blockIdx.x * 256 + threadIdx.x;
    int y = p >> 8, x = p & 255;
    const float* ip = g_h + ((size_t)(b * 732 + c)) * NPIX;
    float wv[9];
#pragma unroll
    for (int i = 0; i < 9; ++i) wv[i] = w[c * 9 + i];
    float acc = 0.f;
#pragma unroll
    for (int dy = 0; dy < 3; ++dy) {
        int yy = y + dy - 1;
        if (yy < 0 || yy > 255) continue;
#pragma unroll
        for (int dx = 0; dx < 3; ++dx) {
            int xx = x + dx - 1;
            if (xx < 0 || xx > 255) continue;
            acc += wv[dy * 3 + dx] * ip[yy * HW + xx];
        }
    }
    g_h2[((size_t)(b * 732 + c)) * NPIX + p] = acc;
}

// ---------------------------------------------------------------------------
// 8x8 circular convolution per patch:  o = irfft2(rfft2(q)*rfft2(k))
// q = g_h2[ch c], k = g_h2[ch 244+c]  ->  o into g_h (compact 244-ch layout)
// 4 patches per 256-thread block.
// ---------------------------------------------------------------------------
__global__ void circ8_kern()
{
    __shared__ float sq[4][64], sk[4][64];
    int pt = threadIdx.x >> 6;
    int t  = threadIdx.x & 63;
    long long pid = (long long)blockIdx.x * 4 + pt;
    int pb = (int)(pid & 1023);
    int bc = (int)(pid >> 10);          // b*244 + c
    int b = bc / 244, c = bc % 244;
    int py = pb >> 5, px = pb & 31;
    int row = t >> 3, col = t & 7;
    size_t qbase = ((size_t)(b * 732 + c)) * NPIX + (py * 8 + row) * HW + px * 8 + col;
    sq[pt][t] = g_h2[qbase];
    sk[pt][t] = g_h2[qbase + (size_t)244 * NPIX];
    __syncthreads();
    int m = row, n = col;
    float acc = 0.f;
#pragma unroll
    for (int i = 0; i < 8; ++i) {
        int km = (m - i) & 7;
#pragma unroll
        for (int j = 0; j < 8; ++j)
            acc += sq[pt][i * 8 + j] * sk[pt][km * 8 + ((n - j) & 7)];
    }
    g_h[((size_t)(b * 244 + c)) * NPIX + (py * 8 + m) * HW + px * 8 + n] = acc;
}

// ---------------------------------------------------------------------------
// LN over 244 channels of o (in g_h), scale by fnw/fnb, multiply by v (g_h2
// channels 488..731), in-place into g_h.
// ---------------------------------------------------------------------------
__global__ void ln2_mul_kern(const float* __restrict__ fnw, const float* __restrict__ fnb)
{
    int t = blockIdx.x * 256 + threadIdx.x;
    if (t >= 2 * NPIX) return;
    int b = t >> 16, p = t & (NPIX - 1);
    float* op = g_h + (size_t)b * 244 * NPIX + p;
    const float* vp = g_h2 + ((size_t)b * 732 + 488) * NPIX + p;
    float sum = 0.f, ss = 0.f;
    for (int c = 0; c < 244; ++c) {
        float v = op[(size_t)c * NPIX];
        sum += v; ss += v * v;
    }
    float mu  = sum * (1.f / 244.f);
    float var = ss * (1.f / 244.f) - mu * mu;
    float rs  = rsqrtf(var + 1e-5f);
    for (int c = 0; c < 244; ++c) {
        float v = op[(size_t)c * NPIX];
        float nrm = (v - mu) * rs * fnw[c] + fnb[c];
        op[(size_t)c * NPIX] = vp[(size_t)c * NPIX] * nrm;
    }
}

// ---------------------------------------------------------------------------
// SE: per (b,c) spatial mean of g_out, then tiny MLP -> g_se
// ---------------------------------------------------------------------------
__global__ void se_mean_kern()
{
    int c = blockIdx.x, b = blockIdx.y;
    const float* p = g_out + ((size_t)b * 122 + c) * NPIX;
    float s = 0.f;
    for (int i = threadIdx.x; i < NPIX; i += 256) s += p[i];
    __shared__ float red[256];
    red[threadIdx.x] = s;
    __syncthreads();
    for (int k = 128; k > 0; k >>= 1) {
        if (threadIdx.x < k) red[threadIdx.x] += red[threadIdx.x + k];
        __syncthreads();
    }
    if (threadIdx.x == 0) g_sey[b * 122 + c] = red[0] * (1.f / (float)NPIX);
}

__global__ void se_mlp_kern(const float* __restrict__ f1, const float* __restrict__ f2)
{
    int b = blockIdx.x;
    __shared__ float ym[122];
    __shared__ float y7[7];
    if (threadIdx.x < 122) ym[threadIdx.x] = g_sey[b * 122 + threadIdx.x];
    __syncthreads();
    if (threadIdx.x < 7) {
        float a = 0.f;
        for (int c = 0; c < 122; ++c) a += f1[threadIdx.x * 122 + c] * ym[c];
        y7[threadIdx.x] = fmaxf(a, 0.f);
    }
    __syncthreads();
    if (threadIdx.x < 122) {
        float a = 0.f;
#pragma unroll
        for (int j = 0; j < 7; ++j) a += f2[threadIdx.x * 7 + j] * y7[j];
        g_se[b * 122 + threadIdx.x] = 1.f / (1.f + expf(-a));
    }
}

// ---------------------------------------------------------------------------
// Soft threshold: z = soft(Wx, c * sigma)   (sigma broadcast over channels)
// ---------------------------------------------------------------------------
__global__ void soft_kern(const float* __restrict__ wx, const float* __restrict__ cth,
                          const float* __restrict__ sigma, float* __restrict__ z)
{
    size_t i = (size_t)blockIdx.x * 256 + threadIdx.x;
    if (i >= (size_t)2 * 121 * NPIX) return;
    int b = (int)(i / ((size_t)121 * NPIX));
    int p = (int)(i & (NPIX - 1));
    float t = cth[i] * sigma[b * NPIX + p];
    float x = wx[i];
    float r = 0.f;
    if (x > t) r = x - t;
    else if (x < -t) r = x + t;
    z[i] = r;
}

// ---------------------------------------------------------------------------
// Output init (w1 copy + zero loss), loss reduction, loss finalize
// ---------------------------------------------------------------------------
__global__ void init_out_kern(const float* __restrict__ w1, float* __restrict__ out)
{
    int i = blockIdx.x * 256 + threadIdx.x;
    if (i < 14641) out[131072 + i] = w1[i];
    if (i == 0) g_loss = 0.0;
}

__global__ void loss_kern()
{
    const size_t N = (size_t)2 * 121 * NPIX;
    double s = 0.0;
    for (size_t i = (size_t)blockIdx.x * 256 + threadIdx.x; i < N; i += (size_t)gridDim.x * 256) {
        float d = g_tA[i] - g_Wx1[i];
        s += (double)d * (double)d;
    }
    __shared__ double red[256];
    red[threadIdx.x] = s;
    __syncthreads();
    for (int k = 128; k > 0; k >>= 1) {
        if (threadIdx.x < k) red[threadIdx.x] += red[threadIdx.x + k];
        __syncthreads();
    }
    if (threadIdx.x == 0) atomicAdd(&g_loss, red[0]);
}

__global__ void loss_fin_kern(float* __restrict__ out)
{
    if (threadIdx.x == 0 && blockIdx.x == 0) out[145713] = (float)g_loss;
}

// ---------------------------------------------------------------------------
// Host orchestration (runs only during graph capture)
// ---------------------------------------------------------------------------
extern "C" void kernel_launch(void* const* d_in, const int* in_sizes, int n_in,
                              void* d_out, int out_size)
{
    const float* input = (const float*)d_in[0];
    const float* sigma = (const float*)d_in[1];
    const float* w1    = (const float*)d_in[2];
    const float* b1    = (const float*)d_in[3];
    const float* w2    = (const float*)d_in[4];
    const float* b2    = (const float*)d_in[5];
    const float* n1w   = (const float*)d_in[6];
    const float* n1b   = (const float*)d_in[7];
    const float* thw   = (const float*)d_in[8];
    const float* tdw   = (const float*)d_in[9];
    const float* fnw   = (const float*)d_in[10];
    const float* fnb   = (const float*)d_in[11];
    const float* pw    = (const float*)d_in[12];
    const float* s1a   = (const float*)d_in[13];
    const float* s1b   = (const float*)d_in[14];
    const float* s2a   = (const float*)d_in[15];
    const float* s2b   = (const float*)d_in[16];
    const float* c1w   = (const float*)d_in[17];
    const float* c1b   = (const float*)d_in[18];
    const float* c2w   = (const float*)d_in[19];
    const float* c2b   = (const float*)d_in[20];
    float* out = (float*)d_out;

    float *pWx1, *pWx2, *pZ, *pTA, *pTB, *pLn, *pH, *pCat, *pOut, *pWT2, *pWT1, *pSe;
    cudaGetSymbolAddress((void**)&pWx1, g_Wx1);
    cudaGetSymbolAddress((void**)&pWx2, g_Wx2);
    cudaGetSymbolAddress((void**)&pZ,   g_z);
    cudaGetSymbolAddress((void**)&pTA,  g_tA);
    cudaGetSymbolAddress((void**)&pTB,  g_tB);
    cudaGetSymbolAddress((void**)&pLn,  g_ln);
    cudaGetSymbolAddress((void**)&pH,   g_h);
    cudaGetSymbolAddress((void**)&pCat, g_cat);
    cudaGetSymbolAddress((void**)&pOut, g_out);
    cudaGetSymbolAddress((void**)&pWT2, g_wT2);
    cudaGetSymbolAddress((void**)&pWT1, g_wT1);
    cudaGetSymbolAddress((void**)&pSe,  g_se);

    const float inv121 = 1.f / 121.f;
    const dim3 blk(256);
    const dim3 gridC121(8, 8, 2 * 16);   // Cout=121 -> 16 co-groups of 8
    const dim3 gridC1(8, 8, 2 * 1);      // Cout=1
    const dim3 gridPix((2 * NPIX) / 256);

    prep_w_kern<<<2048, blk>>>(w1, w2);
    init_out_kern<<<58, blk>>>(w1, out);

    // Wx1 = conv11(rpad(input), w1) + b1
    convK_kern<11, true, false><<<gridC121, blk>>>(input, w1, b1, nullptr, pWx1, 1, 121, 1.f);

    for (int pass = 0; pass < 2; ++pass) {
        const float* wx  = (pass == 0) ? pWx1 : pWx2;
        const float* sea = (pass == 0) ? s1a : s2a;
        const float* seb = (pass == 0) ? s1b : s2b;
        const float* cw  = (pass == 0) ? c1w : c2w;
        const float* cb  = (pass == 0) ? c1b : c2b;

        // TransformerBlock (shared weights)
        ln_cat_kern<<<gridPix, blk>>>(input, wx, n1w, n1b);
        conv1x1_kern<false><<<dim3(256, 46, 2), blk>>>(pLn, thw, nullptr, pH, 122, 732);
        dwconv_kern<<<dim3(256, 732, 2), blk>>>(tdw);
        circ8_kern<<<124928, blk>>>();
        ln2_mul_kern<<<gridPix, blk>>>(fnw, fnb);
        conv1x1_kern<true><<<dim3(256, 8, 2), blk>>>(pH, pw, pCat, pOut, 244, 122);

        // SE -> c (3x3 conv, clip) -> soft threshold
        se_mean_kern<<<dim3(122, 2), blk>>>();
        se_mlp_kern<<<2, 128>>>(sea, seb);
        convK_kern<3, false, true><<<gridC121, blk>>>(pOut, cw, cb, pSe, pTA, 122, 121, 1.f);
        soft_kern<<<61952, blk>>>(wx, pTA, sigma, pZ);

        if (pass == 0) {
            // Wx2 = conv11(rpad(z1), w2) + b2
            convK_kern<11, true, false><<<gridC121, blk>>>(pZ, w2, b2, nullptr, pWx2, 121, 121, 1.f);
        }
    }

    // Wt2 = conv11(rpad(z2), wT2)/121 ; Wt = conv11(rpad(Wt2), wT1)/121
    convK_kern<11, true, false><<<gridC121, blk>>>(pZ, pWT2, nullptr, nullptr, pTA, 121, 121, inv121);
    convK_kern<11, true, false><<<gridC1, blk>>>(pTA, pWT1, nullptr, nullptr, out, 121, 1, inv121);

    // temp = conv11(rpad(Wx1), w2)+b2 ; WTW2 = conv11(rpad(temp), wT2)/121 ; loss
    convK_kern<11, true, false><<<gridC121, blk>>>(pWx1, w2, b2, nullptr, pTB, 121, 121, 1.f);
    convK_kern<11, true, false><<<gridC121, blk>>>(pTB, pWT2, nullptr, nullptr, pTA, 121, 121, inv121);
    loss_kern<<<1024, blk>>>();
    loss_fin_kern<<<1, 32>>>(out);
}

// round 8
// speedup vs baseline: 1.2278x; 1.2278x over previous
#include <cuda_runtime.h>
#include <cstdio>

// ---------------------------------------------------------------------------
// Problem constants
// ---------------------------------------------------------------------------
#define NPIX 65536              // 256*256
#define HW 256

// ---------------------------------------------------------------------------
// Scratch (static __device__ arrays; no allocations allowed)
// ---------------------------------------------------------------------------
__device__ float g_Wx1[2 * 121 * NPIX];
__device__ float g_Wx2[2 * 121 * NPIX];
__device__ float g_z  [2 * 121 * NPIX];
__device__ float g_tA [2 * 121 * NPIX];
__device__ float g_tB [2 * 121 * NPIX];
__device__ float g_cat[2 * 122 * NPIX];
__device__ float g_ln [2 * 122 * NPIX];
__device__ float g_out[2 * 122 * NPIX];
__device__ float g_h  [2 * 732 * NPIX];
__device__ float g_h2 [2 * 732 * NPIX];
__device__ float g_wT2[121 * 121 * 121];
__device__ float g_wT1[121 * 121];
__device__ float g_sey[2 * 122];
__device__ float g_se [2 * 122];
__device__ double g_loss;

__device__ __forceinline__ int refl(int i) {
    i = (i < 0) ? -i : i;
    return (i < HW) ? i : (2 * HW - 2 - i);
}

// Packed fp32x2 helpers (Blackwell FFMA2 — ptxas never auto-fuses; PTX only)
__device__ __forceinline__ unsigned long long pack2(float lo, float hi) {
    unsigned long long r;
    asm("mov.b64 %0, {%1, %2};" : "=l"(r) : "f"(lo), "f"(hi));
    return r;
}
__device__ __forceinline__ void fma2(unsigned long long& acc,
                                     unsigned long long w2,
                                     unsigned long long v2) {
    asm("fma.rn.f32x2 %0, %1, %2, %0;" : "+l"(acc) : "l"(w2), "l"(v2));
}
__device__ __forceinline__ void unpack2(unsigned long long v, float& lo, float& hi) {
    asm("mov.b64 {%0, %1}, %2;" : "=f"(lo), "=f"(hi) : "l"(v));
}

// ---------------------------------------------------------------------------
// Weight prep: wT = rot180(transpose(w))  ->  wT[o][i][tap] = w[i][o][120-tap]
// ---------------------------------------------------------------------------
__global__ void prep_w_kern(const float* __restrict__ w1, const float* __restrict__ w2)
{
    int i0 = blockIdx.x * 256 + threadIdx.x;
    if (i0 < 121 * 121) {
        int ci = i0 / 121, tap = i0 % 121;
        g_wT1[ci * 121 + tap] = w1[ci * 121 + (120 - tap)];
    }
    for (int t = i0; t < 121 * 121 * 121; t += gridDim.x * 256) {
        int co  = t / 14641;
        int rem = t - co * 14641;
        int ci  = rem / 121, tap = rem - ci * 121;
        g_wT2[(co * 121 + ci) * 121 + tap] = w2[(ci * 121 + co) * 121 + (120 - tap)];
    }
}

// ---------------------------------------------------------------------------
// Generic KSxKS conv (cross-correlation), 32x32 output tile, 8 co / block.
// Inner loop uses packed fma.rn.f32x2: acc pairs along output channels, so
// weight pairs come pre-packed from s_w8 via 8B-aligned 64-bit LDS.
// REFLECT: reflect padding (pad=KS/2) ; else zero pad.
// chscale: optional per-(b,ci) input scale (SE). CLIP: clamp [0,10] after bias.
// ---------------------------------------------------------------------------
template<int KS, bool REFLECT, bool CLIP>
__global__ void __launch_bounds__(256) convK_kern(
    const float* __restrict__ in, const float* __restrict__ wbuf,
    const float* __restrict__ bias, const float* __restrict__ chscale,
    float* __restrict__ out, int Cin, int Cout, float outscale)
{
    constexpr int PAD = KS / 2;
    constexpr int IN  = 32 + KS - 1;
    constexpr int STR = IN + 1;          // odd stride -> conflict-free 2-row access
    constexpr int KK  = KS * KS;
    // 16B-aligned: read via 64-bit (and the base must suit wide LDS).
    __shared__ __align__(16) float s_w8[KK * 8];   // [tap][8 co]
    __shared__ float s_in[IN * STR];

    const int nCoG = (Cout + 7) >> 3;
    const int b    = blockIdx.z / nCoG;
    const int cog  = blockIdx.z % nCoG;
    const int by = blockIdx.y, bx = blockIdx.x;
    const int tid = threadIdx.x;
    const int ty = tid >> 4, tx = tid & 15;
    const int r0 = ty * 2, c0 = tx * 2;

    // acc2[pixel][co-pair] : packed (co 2q, co 2q+1)
    unsigned long long acc2[4][4];
#pragma unroll
    for (int p = 0; p < 4; ++p)
#pragma unroll
        for (int q = 0; q < 4; ++q) acc2[p][q] = 0ull;

    const size_t inBase  = (size_t)b * Cin * NPIX;
    const int    co0     = cog * 8;
    const size_t wstride = (size_t)Cin * KK;

    for (int ci = 0; ci < Cin; ++ci) {
        const float* ip = in + inBase + (size_t)ci * NPIX;
        float sc = 1.f;
        if (chscale) sc = chscale[b * Cin + ci];
        for (int idx = tid; idx < IN * IN; idx += 256) {
            int row = idx / IN, col = idx - row * IN;
            int gy = by * 32 + row - PAD;
            int gx = bx * 32 + col - PAD;
            float v;
            if (REFLECT) {
                v = ip[refl(gy) * HW + refl(gx)];
            } else {
                v = (gy >= 0 && gy < HW && gx >= 0 && gx < HW) ? ip[gy * HW + gx] : 0.f;
            }
            s_in[row * STR + col] = v * sc;
        }
        {
            const float* wci = wbuf + (size_t)ci * KK;
            for (int t = tid; t < KK * 8; t += 256) {
                int tap = t >> 3, j = t & 7;
                int co  = co0 + j;
                int cosafe = (co < Cout) ? co : (Cout - 1);
                float wv = wci[(size_t)cosafe * wstride + tap];
                s_w8[t] = (co < Cout) ? wv : 0.f;
            }
        }
        __syncthreads();
#pragma unroll 1
        for (int r = 0; r < KS; ++r) {
            const float* p0 = &s_in[(r0 + r) * STR + c0];
            const float* p1 = p0 + STR;
#pragma unroll
            for (int s = 0; s < KS; ++s) {
                const unsigned long long* wq =
                    (const unsigned long long*)&s_w8[(r * KS + s) * 8];
                unsigned long long w01 = wq[0], w23 = wq[1];
                unsigned long long w45 = wq[2], w67 = wq[3];
                unsigned long long v00 = pack2(p0[s], p0[s]);
                unsigned long long v01 = pack2(p0[s + 1], p0[s + 1]);
                unsigned long long v10 = pack2(p1[s], p1[s]);
                unsigned long long v11 = pack2(p1[s + 1], p1[s + 1]);
                fma2(acc2[0][0], w01, v00); fma2(acc2[0][1], w23, v00);
                fma2(acc2[0][2], w45, v00); fma2(acc2[0][3], w67, v00);
                fma2(acc2[1][0], w01, v01); fma2(acc2[1][1], w23, v01);
                fma2(acc2[1][2], w45, v01); fma2(acc2[1][3], w67, v01);
                fma2(acc2[2][0], w01, v10); fma2(acc2[2][1], w23, v10);
                fma2(acc2[2][2], w45, v10); fma2(acc2[2][3], w67, v10);
                fma2(acc2[3][0], w01, v11); fma2(acc2[3][1], w23, v11);
                fma2(acc2[3][2], w45, v11); fma2(acc2[3][3], w67, v11);
            }
        }
        __syncthreads();
    }

    // Unpack to scalar accumulators
    float acc[4][8];
#pragma unroll
    for (int p = 0; p < 4; ++p)
#pragma unroll
        for (int q = 0; q < 4; ++q)
            unpack2(acc2[p][q], acc[p][2 * q], acc[p][2 * q + 1]);

    const int oy = by * 32 + r0, ox = bx * 32 + c0;
    const size_t outBase = (size_t)b * Cout * NPIX;
#pragma unroll
    for (int j = 0; j < 8; ++j) {
        int co = co0 + j;
        if (co >= Cout) break;
        float bv = bias ? bias[co] : 0.f;
        float* op = out + outBase + (size_t)co * NPIX;
        float r00 = acc[0][j] * outscale + bv;
        float r01 = acc[1][j] * outscale + bv;
        float r10 = acc[2][j] * outscale + bv;
        float r11 = acc[3][j] * outscale + bv;
        if (CLIP) {
            r00 = fminf(fmaxf(r00, 0.f), 10.f);
            r01 = fminf(fmaxf(r01, 0.f), 10.f);
            r10 = fminf(fmaxf(r10, 0.f), 10.f);
            r11 = fminf(fmaxf(r11, 0.f), 10.f);
        }
        op[oy * HW + ox]           = r00;
        op[oy * HW + ox + 1]       = r01;
        op[(oy + 1) * HW + ox]     = r10;
        op[(oy + 1) * HW + ox + 1] = r11;
    }
}

// ---------------------------------------------------------------------------
// 1x1 conv (channel GEMM). 256 px/block, 16 co/block. Optional residual add.
// ---------------------------------------------------------------------------
template<bool RESID>
__global__ void __launch_bounds__(256) conv1x1_kern(
    const float* __restrict__ x, const float* __restrict__ w,
    const float* __restrict__ resid, float* __restrict__ out,
    int Cin, int Cout)
{
    __shared__ float4 s_w[244 * 4];
    const int b   = blockIdx.z;
    const int co0 = blockIdx.y * 16;
    const int px  = blockIdx.x * 256 + threadIdx.x;
    for (int t = threadIdx.x; t < Cin * 4; t += 256) {
        int ci = t >> 2, g = t & 3;
        int co = co0 + g * 4;
        float4 v;
        v.x = (co + 0 < Cout) ? w[(size_t)(co + 0) * Cin + ci] : 0.f;
        v.y = (co + 1 < Cout) ? w[(size_t)(co + 1) * Cin + ci] : 0.f;
        v.z = (co + 2 < Cout) ? w[(size_t)(co + 2) * Cin + ci] : 0.f;
        v.w = (co + 3 < Cout) ? w[(size_t)(co + 3) * Cin + ci] : 0.f;
        s_w[t] = v;
    }
    __syncthreads();
    float acc[16];
#pragma unroll
    for (int j = 0; j < 16; ++j) acc[j] = 0.f;
    const float* xp = x + (size_t)b * Cin * NPIX + px;
#pragma unroll 2
    for (int ci = 0; ci < Cin; ++ci) {
        float xv = xp[(size_t)ci * NPIX];
#pragma unroll
        for (int g = 0; g < 4; ++g) {
            float4 w4 = s_w[ci * 4 + g];
            acc[g * 4 + 0] += w4.x * xv;
            acc[g * 4 + 1] += w4.y * xv;
            acc[g * 4 + 2] += w4.z * xv;
            acc[g * 4 + 3] += w4.w * xv;
        }
    }
    const size_t ob = (size_t)b * Cout * NPIX + px;
#pragma unroll
    for (int j = 0; j < 16; ++j) {
        int co = co0 + j;
        if (co < Cout) {
            float v = acc[j];
            if (RESID) v += resid[ob + (size_t)co * NPIX];
            out[ob + (size_t)co * NPIX] = v;
        }
    }
}

// ---------------------------------------------------------------------------
// LayerNorm over 122 channels of concat([input, Wx]) per pixel.
// Writes both cat (for residual) and ln.
// ---------------------------------------------------------------------------
__global__ void ln_cat_kern(const float* __restrict__ in0, const float* __restrict__ wx,
                            const float* __restrict__ gw, const float* __restrict__ gb)
{
    int t = blockIdx.x * 256 + threadIdx.x;
    if (t >= 2 * NPIX) return;
    int b = t >> 16, p = t & (NPIX - 1);
    float x0 = in0[t];
    const float* wp = wx + (size_t)b * 121 * NPIX + p;
    float sum = x0, ss = x0 * x0;
    for (int c = 0; c < 121; ++c) {
        float v = wp[(size_t)c * NPIX];
        sum += v; ss += v * v;
    }
    float mu  = sum * (1.f / 122.f);
    float var = ss * (1.f / 122.f) - mu * mu;
    float rs  = rsqrtf(var + 1e-5f);
    size_t base = (size_t)b * 122 * NPIX + p;
    g_cat[base] = x0;
    g_ln[base]  = (x0 - mu) * rs * gw[0] + gb[0];
    for (int c = 0; c < 121; ++c) {
        float v = wp[(size_t)c * NPIX];
        g_cat[base + (size_t)(c + 1) * NPIX] = v;
        g_ln[base + (size_t)(c + 1) * NPIX]  = (v - mu) * rs * gw[c + 1] + gb[c + 1];
    }
}

// ---------------------------------------------------------------------------
// Depthwise 3x3, zero pad, 732 channels: g_h -> g_h2
// ---------------------------------------------------------------------------
__global__ void dwconv_kern(const float* __restrict__ w)
{
    int c = blockIdx.y, b = blockIdx.z;
    int p = blockIdx.x * 256 + threadIdx.x;
    int y = p >> 8, x = p & 255;
    const float* ip = g_h + ((size_t)(b * 732 + c)) * NPIX;
    float wv[9];
#pragma unroll
    for (int i = 0; i < 9; ++i) wv[i] = w[c * 9 + i];
    float acc = 0.f;
#pragma unroll
    for (int dy = 0; dy < 3; ++dy) {
        int yy = y + dy - 1;
        if (yy < 0 || yy > 255) continue;
#pragma unroll
        for (int dx = 0; dx < 3; ++dx) {
            int xx = x + dx - 1;
            if (xx < 0 || xx > 255) continue;
            acc += wv[dy * 3 + dx] * ip[yy * HW + xx];
        }
    }
    g_h2[((size_t)(b * 732 + c)) * NPIX + p] = acc;
}

// ---------------------------------------------------------------------------
// 8x8 circular convolution per patch:  o = irfft2(rfft2(q)*rfft2(k))
// q = g_h2[ch c], k = g_h2[ch 244+c]  ->  o into g_h (compact 244-ch layout)
// 4 patches per 256-thread block.
// ---------------------------------------------------------------------------
__global__ void circ8_kern()
{
    __shared__ float sq[4][64], sk[4][64];
    int pt = threadIdx.x >> 6;
    int t  = threadIdx.x & 63;
    long long pid = (long long)blockIdx.x * 4 + pt;
    int pb = (int)(pid & 1023);
    int bc = (int)(pid >> 10);          // b*244 + c
    int b = bc / 244, c = bc % 244;
    int py = pb >> 5, px = pb & 31;
    int row = t >> 3, col = t & 7;
    size_t qbase = ((size_t)(b * 732 + c)) * NPIX + (py * 8 + row) * HW + px * 8 + col;
    sq[pt][t] = g_h2[qbase];
    sk[pt][t] = g_h2[qbase + (size_t)244 * NPIX];
    __syncthreads();
    int m = row, n = col;
    float acc = 0.f;
#pragma unroll
    for (int i = 0; i < 8; ++i) {
        int km = (m - i) & 7;
#pragma unroll
        for (int j = 0; j < 8; ++j)
            acc += sq[pt][i * 8 + j] * sk[pt][km * 8 + ((n - j) & 7)];
    }
    g_h[((size_t)(b * 244 + c)) * NPIX + (py * 8 + m) * HW + px * 8 + n] = acc;
}

// ---------------------------------------------------------------------------
// LN over 244 channels of o (in g_h), scale by fnw/fnb, multiply by v (g_h2
// channels 488..731), in-place into g_h.
// ---------------------------------------------------------------------------
__global__ void ln2_mul_kern(const float* __restrict__ fnw, const float* __restrict__ fnb)
{
    int t = blockIdx.x * 256 + threadIdx.x;
    if (t >= 2 * NPIX) return;
    int b = t >> 16, p = t & (NPIX - 1);
    float* op = g_h + (size_t)b * 244 * NPIX + p;
    const float* vp = g_h2 + ((size_t)b * 732 + 488) * NPIX + p;
    float sum = 0.f, ss = 0.f;
    for (int c = 0; c < 244; ++c) {
        float v = op[(size_t)c * NPIX];
        sum += v; ss += v * v;
    }
    float mu  = sum * (1.f / 244.f);
    float var = ss * (1.f / 244.f) - mu * mu;
    float rs  = rsqrtf(var + 1e-5f);
    for (int c = 0; c < 244; ++c) {
        float v = op[(size_t)c * NPIX];
        float nrm = (v - mu) * rs * fnw[c] + fnb[c];
        op[(size_t)c * NPIX] = vp[(size_t)c * NPIX] * nrm;
    }
}

// ---------------------------------------------------------------------------
// SE: per (b,c) spatial mean of g_out, then tiny MLP -> g_se
// ---------------------------------------------------------------------------
__global__ void se_mean_kern()
{
    int c = blockIdx.x, b = blockIdx.y;
    const float* p = g_out + ((size_t)b * 122 + c) * NPIX;
    float s = 0.f;
    for (int i = threadIdx.x; i < NPIX; i += 256) s += p[i];
    __shared__ float red[256];
    red[threadIdx.x] = s;
    __syncthreads();
    for (int k = 128; k > 0; k >>= 1) {
        if (threadIdx.x < k) red[threadIdx.x] += red[threadIdx.x + k];
        __syncthreads();
    }
    if (threadIdx.x == 0) g_sey[b * 122 + c] = red[0] * (1.f / (float)NPIX);
}

__global__ void se_mlp_kern(const float* __restrict__ f1, const float* __restrict__ f2)
{
    int b = blockIdx.x;
    __shared__ float ym[122];
    __shared__ float y7[7];
    if (threadIdx.x < 122) ym[threadIdx.x] = g_sey[b * 122 + threadIdx.x];
    __syncthreads();
    if (threadIdx.x < 7) {
        float a = 0.f;
        for (int c = 0; c < 122; ++c) a += f1[threadIdx.x * 122 + c] * ym[c];
        y7[threadIdx.x] = fmaxf(a, 0.f);
    }
    __syncthreads();
    if (threadIdx.x < 122) {
        float a = 0.f;
#pragma unroll
        for (int j = 0; j < 7; ++j) a += f2[threadIdx.x * 7 + j] * y7[j];
        g_se[b * 122 + threadIdx.x] = 1.f / (1.f + expf(-a));
    }
}

// ---------------------------------------------------------------------------
// Soft threshold: z = soft(Wx, c * sigma)   (sigma broadcast over channels)
// ---------------------------------------------------------------------------
__global__ void soft_kern(const float* __restrict__ wx, const float* __restrict__ cth,
                          const float* __restrict__ sigma, float* __restrict__ z)
{
    size_t i = (size_t)blockIdx.x * 256 + threadIdx.x;
    if (i >= (size_t)2 * 121 * NPIX) return;
    int b = (int)(i / ((size_t)121 * NPIX));
    int p = (int)(i & (NPIX - 1));
    float t = cth[i] * sigma[b * NPIX + p];
    float x = wx[i];
    float r = 0.f;
    if (x > t) r = x - t;
    else if (x < -t) r = x + t;
    z[i] = r;
}

// ---------------------------------------------------------------------------
// Output init (w1 copy + zero loss), loss reduction, loss finalize
// ---------------------------------------------------------------------------
__global__ void init_out_kern(const float* __restrict__ w1, float* __restrict__ out)
{
    int i = blockIdx.x * 256 + threadIdx.x;
    if (i < 14641) out[131072 + i] = w1[i];
    if (i == 0) g_loss = 0.0;
}

__global__ void loss_kern()
{
    const size_t N = (size_t)2 * 121 * NPIX;
    double s = 0.0;
    for (size_t i = (size_t)blockIdx.x * 256 + threadIdx.x; i < N; i += (size_t)gridDim.x * 256) {
        float d = g_tA[i] - g_Wx1[i];
        s += (double)d * (double)d;
    }
    __shared__ double red[256];
    red[threadIdx.x] = s;
    __syncthreads();
    for (int k = 128; k > 0; k >>= 1) {
        if (threadIdx.x < k) red[threadIdx.x] += red[threadIdx.x + k];
        __syncthreads();
    }
    if (threadIdx.x == 0) atomicAdd(&g_loss, red[0]);
}

__global__ void loss_fin_kern(float* __restrict__ out)
{
    if (threadIdx.x == 0 && blockIdx.x == 0) out[145713] = (float)g_loss;
}

// ---------------------------------------------------------------------------
// Host orchestration (runs only during graph capture)
// ---------------------------------------------------------------------------
extern "C" void kernel_launch(void* const* d_in, const int* in_sizes, int n_in,
                              void* d_out, int out_size)
{
    const float* input = (const float*)d_in[0];
    const float* sigma = (const float*)d_in[1];
    const float* w1    = (const float*)d_in[2];
    const float* b1    = (const float*)d_in[3];
    const float* w2    = (const float*)d_in[4];
    const float* b2    = (const float*)d_in[5];
    const float* n1w   = (const float*)d_in[6];
    const float* n1b   = (const float*)d_in[7];
    const float* thw   = (const float*)d_in[8];
    const float* tdw   = (const float*)d_in[9];
    const float* fnw   = (const float*)d_in[10];
    const float* fnb   = (const float*)d_in[11];
    const float* pw    = (const float*)d_in[12];
    const float* s1a   = (const float*)d_in[13];
    const float* s1b   = (const float*)d_in[14];
    const float* s2a   = (const float*)d_in[15];
    const float* s2b   = (const float*)d_in[16];
    const float* c1w   = (const float*)d_in[17];
    const float* c1b   = (const float*)d_in[18];
    const float* c2w   = (const float*)d_in[19];
    const float* c2b   = (const float*)d_in[20];
    float* out = (float*)d_out;

    float *pWx1, *pWx2, *pZ, *pTA, *pTB, *pLn, *pH, *pCat, *pOut, *pWT2, *pWT1, *pSe;
    cudaGetSymbolAddress((void**)&pWx1, g_Wx1);
    cudaGetSymbolAddress((void**)&pWx2, g_Wx2);
    cudaGetSymbolAddress((void**)&pZ,   g_z);
    cudaGetSymbolAddress((void**)&pTA,  g_tA);
    cudaGetSymbolAddress((void**)&pTB,  g_tB);
    cudaGetSymbolAddress((void**)&pLn,  g_ln);
    cudaGetSymbolAddress((void**)&pH,   g_h);
    cudaGetSymbolAddress((void**)&pCat, g_cat);
    cudaGetSymbolAddress((void**)&pOut, g_out);
    cudaGetSymbolAddress((void**)&pWT2, g_wT2);
    cudaGetSymbolAddress((void**)&pWT1, g_wT1);
    cudaGetSymbolAddress((void**)&pSe,  g_se);

    const float inv121 = 1.f / 121.f;
    const dim3 blk(256);
    const dim3 gridC121(8, 8, 2 * 16);   // Cout=121 -> 16 co-groups of 8
    const dim3 gridC1(8, 8, 2 * 1);      // Cout=1
    const dim3 gridPix((2 * NPIX) / 256);

    prep_w_kern<<<2048, blk>>>(w1, w2);
    init_out_kern<<<58, blk>>>(w1, out);

    // Wx1 = conv11(rpad(input), w1) + b1
    convK_kern<11, true, false><<<gridC121, blk>>>(input, w1, b1, nullptr, pWx1, 1, 121, 1.f);

    for (int pass = 0; pass < 2; ++pass) {
        const float* wx  = (pass == 0) ? pWx1 : pWx2;
        const float* sea = (pass == 0) ? s1a : s2a;
        const float* seb = (pass == 0) ? s1b : s2b;
        const float* cw  = (pass == 0) ? c1w : c2w;
        const float* cb  = (pass == 0) ? c1b : c2b;

        // TransformerBlock (shared weights)
        ln_cat_kern<<<gridPix, blk>>>(input, wx, n1w, n1b);
        conv1x1_kern<false><<<dim3(256, 46, 2), blk>>>(pLn, thw, nullptr, pH, 122, 732);
        dwconv_kern<<<dim3(256, 732, 2), blk>>>(tdw);
        circ8_kern<<<124928, blk>>>();
        ln2_mul_kern<<<gridPix, blk>>>(fnw, fnb);
        conv1x1_kern<true><<<dim3(256, 8, 2), blk>>>(pH, pw, pCat, pOut, 244, 122);

        // SE -> c (3x3 conv, clip) -> soft threshold
        se_mean_kern<<<dim3(122, 2), blk>>>();
        se_mlp_kern<<<2, 128>>>(sea, seb);
        convK_kern<3, false, true><<<gridC121, blk>>>(pOut, cw, cb, pSe, pTA, 122, 121, 1.f);
        soft_kern<<<61952, blk>>>(wx, pTA, sigma, pZ);

        if (pass == 0) {
            // Wx2 = conv11(rpad(z1), w2) + b2
            convK_kern<11, true, false><<<gridC121, blk>>>(pZ, w2, b2, nullptr, pWx2, 121, 121, 1.f);
        }
    }

    // Wt2 = conv11(rpad(z2), wT2)/121 ; Wt = conv11(rpad(Wt2), wT1)/121
    convK_kern<11, true, false><<<gridC121, blk>>>(pZ, pWT2, nullptr, nullptr, pTA, 121, 121, inv121);
    convK_kern<11, true, false><<<gridC1, blk>>>(pTA, pWT1, nullptr, nullptr, out, 121, 1, inv121);

    // temp = conv11(rpad(Wx1), w2)+b2 ; WTW2 = conv11(rpad(temp), wT2)/121 ; loss
    convK_kern<11, true, false><<<gridC121, blk>>>(pWx1, w2, b2, nullptr, pTB, 121, 121, 1.f);
    convK_kern<11, true, false><<<gridC121, blk>>>(pTB, pWT2, nullptr, nullptr, pTA, 121, 121, inv121);
    loss_kern<<<1024, blk>>>();
    loss_fin_kern<<<1, 32>>>(out);
}

// round 9
// speedup vs baseline: 1.2285x; 1.0006x over previous
#include <cuda_runtime.h>
#include <cstdio>

// ---------------------------------------------------------------------------
// Problem constants
// ---------------------------------------------------------------------------
#define NPIX 65536              // 256*256
#define HW 256

// ---------------------------------------------------------------------------
// Scratch (static __device__ arrays; no allocations allowed)
// ---------------------------------------------------------------------------
__device__ float g_Wx1[2 * 121 * NPIX];
__device__ float g_Wx2[2 * 121 * NPIX];
__device__ float g_z  [2 * 121 * NPIX];
__device__ float g_tA [2 * 121 * NPIX];
__device__ float g_tB [2 * 121 * NPIX];
__device__ float g_cat[2 * 122 * NPIX];
__device__ float g_ln [2 * 122 * NPIX];
__device__ float g_out[2 * 122 * NPIX];
__device__ float g_h  [2 * 732 * NPIX];
__device__ float g_h2 [2 * 732 * NPIX];
__device__ float g_wT2[121 * 121 * 121];
__device__ float g_wT1[121 * 121];
__device__ float g_sey[2 * 122];
__device__ float g_se [2 * 122];
__device__ double g_loss;

__device__ __forceinline__ int refl(int i) {
    i = (i < 0) ? -i : i;
    return (i < HW) ? i : (2 * HW - 2 - i);
}

// Packed fp32x2 helpers (Blackwell FFMA2 — ptxas never auto-fuses; PTX only)
__device__ __forceinline__ unsigned long long pack2(float lo, float hi) {
    unsigned long long r;
    asm("mov.b64 %0, {%1, %2};" : "=l"(r) : "f"(lo), "f"(hi));
    return r;
}
__device__ __forceinline__ void fma2(unsigned long long& acc,
                                     unsigned long long w2,
                                     unsigned long long v2) {
    asm("fma.rn.f32x2 %0, %1, %2, %0;" : "+l"(acc) : "l"(w2), "l"(v2));
}
__device__ __forceinline__ void unpack2(unsigned long long v, float& lo, float& hi) {
    asm("mov.b64 {%0, %1}, %2;" : "=f"(lo), "=f"(hi) : "l"(v));
}

// ---------------------------------------------------------------------------
// Weight prep: wT = rot180(transpose(w))  ->  wT[o][i][tap] = w[i][o][120-tap]
// ---------------------------------------------------------------------------
__global__ void prep_w_kern(const float* __restrict__ w1, const float* __restrict__ w2)
{
    int i0 = blockIdx.x * 256 + threadIdx.x;
    if (i0 < 121 * 121) {
        int ci = i0 / 121, tap = i0 % 121;
        g_wT1[ci * 121 + tap] = w1[ci * 121 + (120 - tap)];
    }
    for (int t = i0; t < 121 * 121 * 121; t += gridDim.x * 256) {
        int co  = t / 14641;
        int rem = t - co * 14641;
        int ci  = rem / 121, tap = rem - ci * 121;
        g_wT2[(co * 121 + ci) * 121 + tap] = w2[(ci * 121 + co) * 121 + (120 - tap)];
    }
}

// ---------------------------------------------------------------------------
// Generic KSxKS conv (cross-correlation), 32x32 output tile, 8 co / block.
// Inner loop uses packed fma.rn.f32x2: acc pairs along output channels, so
// weight pairs come pre-packed from s_w8 via 8B-aligned 64-bit LDS.
// REFLECT: reflect padding (pad=KS/2) ; else zero pad.
// chscale: optional per-(b,ci) input scale (SE). CLIP: clamp [0,10] after bias.
// ---------------------------------------------------------------------------
template<int KS, bool REFLECT, bool CLIP>
__global__ void __launch_bounds__(256) convK_kern(
    const float* __restrict__ in, const float* __restrict__ wbuf,
    const float* __restrict__ bias, const float* __restrict__ chscale,
    float* __restrict__ out, int Cin, int Cout, float outscale)
{
    constexpr int PAD = KS / 2;
    constexpr int IN  = 32 + KS - 1;
    constexpr int STR = IN + 1;          // odd stride -> conflict-free 2-row access
    constexpr int KK  = KS * KS;
    // 16B-aligned: read via 64-bit (and the base must suit wide LDS).
    __shared__ __align__(16) float s_w8[KK * 8];   // [tap][8 co]
    __shared__ float s_in[IN * STR];

    const int nCoG = (Cout + 7) >> 3;
    const int b    = blockIdx.z / nCoG;
    const int cog  = blockIdx.z % nCoG;
    const int by = blockIdx.y, bx = blockIdx.x;
    const int tid = threadIdx.x;
    const int ty = tid >> 4, tx = tid & 15;
    const int r0 = ty * 2, c0 = tx * 2;

    // acc2[pixel][co-pair] : packed (co 2q, co 2q+1)
    unsigned long long acc2[4][4];
#pragma unroll
    for (int p = 0; p < 4; ++p)
#pragma unroll
        for (int q = 0; q < 4; ++q) acc2[p][q] = 0ull;

    const size_t inBase  = (size_t)b * Cin * NPIX;
    const int    co0     = cog * 8;
    const size_t wstride = (size_t)Cin * KK;

    for (int ci = 0; ci < Cin; ++ci) {
        const float* ip = in + inBase + (size_t)ci * NPIX;
        float sc = 1.f;
        if (chscale) sc = chscale[b * Cin + ci];
        for (int idx = tid; idx < IN * IN; idx += 256) {
            int row = idx / IN, col = idx - row * IN;
            int gy = by * 32 + row - PAD;
            int gx = bx * 32 + col - PAD;
            float v;
            if (REFLECT) {
                v = ip[refl(gy) * HW + refl(gx)];
            } else {
                v = (gy >= 0 && gy < HW && gx >= 0 && gx < HW) ? ip[gy * HW + gx] : 0.f;
            }
            s_in[row * STR + col] = v * sc;
        }
        {
            const float* wci = wbuf + (size_t)ci * KK;
            for (int t = tid; t < KK * 8; t += 256) {
                int tap = t >> 3, j = t & 7;
                int co  = co0 + j;
                int cosafe = (co < Cout) ? co : (Cout - 1);
                float wv = wci[(size_t)cosafe * wstride + tap];
                s_w8[t] = (co < Cout) ? wv : 0.f;
            }
        }
        __syncthreads();
#pragma unroll 1
        for (int r = 0; r < KS; ++r) {
            const float* p0 = &s_in[(r0 + r) * STR + c0];
            const float* p1 = p0 + STR;
#pragma unroll
            for (int s = 0; s < KS; ++s) {
                const unsigned long long* wq =
                    (const unsigned long long*)&s_w8[(r * KS + s) * 8];
                unsigned long long w01 = wq[0], w23 = wq[1];
                unsigned long long w45 = wq[2], w67 = wq[3];
                unsigned long long v00 = pack2(p0[s], p0[s]);
                unsigned long long v01 = pack2(p0[s + 1], p0[s + 1]);
                unsigned long long v10 = pack2(p1[s], p1[s]);
                unsigned long long v11 = pack2(p1[s + 1], p1[s + 1]);
                fma2(acc2[0][0], w01, v00); fma2(acc2[0][1], w23, v00);
                fma2(acc2[0][2], w45, v00); fma2(acc2[0][3], w67, v00);
                fma2(acc2[1][0], w01, v01); fma2(acc2[1][1], w23, v01);
                fma2(acc2[1][2], w45, v01); fma2(acc2[1][3], w67, v01);
                fma2(acc2[2][0], w01, v10); fma2(acc2[2][1], w23, v10);
                fma2(acc2[2][2], w45, v10); fma2(acc2[2][3], w67, v10);
                fma2(acc2[3][0], w01, v11); fma2(acc2[3][1], w23, v11);
                fma2(acc2[3][2], w45, v11); fma2(acc2[3][3], w67, v11);
            }
        }
        __syncthreads();
    }

    // Unpack to scalar accumulators
    float acc[4][8];
#pragma unroll
    for (int p = 0; p < 4; ++p)
#pragma unroll
        for (int q = 0; q < 4; ++q)
            unpack2(acc2[p][q], acc[p][2 * q], acc[p][2 * q + 1]);

    const int oy = by * 32 + r0, ox = bx * 32 + c0;
    const size_t outBase = (size_t)b * Cout * NPIX;
#pragma unroll
    for (int j = 0; j < 8; ++j) {
        int co = co0 + j;
        if (co >= Cout) break;
        float bv = bias ? bias[co] : 0.f;
        float* op = out + outBase + (size_t)co * NPIX;
        float r00 = acc[0][j] * outscale + bv;
        float r01 = acc[1][j] * outscale + bv;
        float r10 = acc[2][j] * outscale + bv;
        float r11 = acc[3][j] * outscale + bv;
        if (CLIP) {
            r00 = fminf(fmaxf(r00, 0.f), 10.f);
            r01 = fminf(fmaxf(r01, 0.f), 10.f);
            r10 = fminf(fmaxf(r10, 0.f), 10.f);
            r11 = fminf(fmaxf(r11, 0.f), 10.f);
        }
        op[oy * HW + ox]           = r00;
        op[oy * HW + ox + 1]       = r01;
        op[(oy + 1) * HW + ox]     = r10;
        op[(oy + 1) * HW + ox + 1] = r11;
    }
}

// ---------------------------------------------------------------------------
// 1x1 conv (channel GEMM). 256 px/block, 16 co/block. Optional residual add.
// ---------------------------------------------------------------------------
template<bool RESID>
__global__ void __launch_bounds__(256) conv1x1_kern(
    const float* __restrict__ x, const float* __restrict__ w,
    const float* __restrict__ resid, float* __restrict__ out,
    int Cin, int Cout)
{
    __shared__ float4 s_w[244 * 4];
    const int b   = blockIdx.z;
    const int co0 = blockIdx.y * 16;
    const int px  = blockIdx.x * 256 + threadIdx.x;
    for (int t = threadIdx.x; t < Cin * 4; t += 256) {
        int ci = t >> 2, g = t & 3;
        int co = co0 + g * 4;
        float4 v;
        v.x = (co + 0 < Cout) ? w[(size_t)(co + 0) * Cin + ci] : 0.f;
        v.y = (co + 1 < Cout) ? w[(size_t)(co + 1) * Cin + ci] : 0.f;
        v.z = (co + 2 < Cout) ? w[(size_t)(co + 2) * Cin + ci] : 0.f;
        v.w = (co + 3 < Cout) ? w[(size_t)(co + 3) * Cin + ci] : 0.f;
        s_w[t] = v;
    }
    __syncthreads();
    float acc[16];
#pragma unroll
    for (int j = 0; j < 16; ++j) acc[j] = 0.f;
    const float* xp = x + (size_t)b * Cin * NPIX + px;
#pragma unroll 2
    for (int ci = 0; ci < Cin; ++ci) {
        float xv = xp[(size_t)ci * NPIX];
#pragma unroll
        for (int g = 0; g < 4; ++g) {
            float4 w4 = s_w[ci * 4 + g];
            acc[g * 4 + 0] += w4.x * xv;
            acc[g * 4 + 1] += w4.y * xv;
            acc[g * 4 + 2] += w4.z * xv;
            acc[g * 4 + 3] += w4.w * xv;
        }
    }
    const size_t ob = (size_t)b * Cout * NPIX + px;
#pragma unroll
    for (int j = 0; j < 16; ++j) {
        int co = co0 + j;
        if (co < Cout) {
            float v = acc[j];
            if (RESID) v += resid[ob + (size_t)co * NPIX];
            out[ob + (size_t)co * NPIX] = v;
        }
    }
}

// ---------------------------------------------------------------------------
// LayerNorm over 122 channels of concat([input, Wx]) per pixel.
// Writes both cat (for residual) and ln.
// ---------------------------------------------------------------------------
__global__ void ln_cat_kern(const float* __restrict__ in0, const float* __restrict__ wx,
                            const float* __restrict__ gw, const float* __restrict__ gb)
{
    int t = blockIdx.x * 256 + threadIdx.x;
    if (t >= 2 * NPIX) return;
    int b = t >> 16, p = t & (NPIX - 1);
    float x0 = in0[t];
    const float* wp = wx + (size_t)b * 121 * NPIX + p;
    float sum = x0, ss = x0 * x0;
    for (int c = 0; c < 121; ++c) {
        float v = wp[(size_t)c * NPIX];
        sum += v; ss += v * v;
    }
    float mu  = sum * (1.f / 122.f);
    float var = ss * (1.f / 122.f) - mu * mu;
    float rs  = rsqrtf(var + 1e-5f);
    size_t base = (size_t)b * 122 * NPIX + p;
    g_cat[base] = x0;
    g_ln[base]  = (x0 - mu) * rs * gw[0] + gb[0];
    for (int c = 0; c < 121; ++c) {
        float v = wp[(size_t)c * NPIX];
        g_cat[base + (size_t)(c + 1) * NPIX] = v;
        g_ln[base + (size_t)(c + 1) * NPIX]  = (v - mu) * rs * gw[c + 1] + gb[c + 1];
    }
}

// ---------------------------------------------------------------------------
// Depthwise 3x3, zero pad, 732 channels: g_h -> g_h2
// ---------------------------------------------------------------------------
__global__ void dwconv_kern(const float* __restrict__ w)
{
    int c = blockIdx.y, b = blockIdx.z;
    int p = blockIdx.x * 256 + threadIdx.x;
    int y = p >> 8, x = p & 255;
    const float* ip = g_h + ((size_t)(b * 732 + c)) * NPIX;
    float wv[9];
#pragma unroll
    for (int i = 0; i < 9; ++i) wv[i] = w[c * 9 + i];
    float acc = 0.f;
#pragma unroll
    for (int dy = 0; dy < 3; ++dy) {
        int yy = y + dy - 1;
        if (yy < 0 || yy > 255) continue;
#pragma unroll
        for (int dx = 0; dx < 3; ++dx) {
            int xx = x + dx - 1;
            if (xx < 0 || xx > 255) continue;
            acc += wv[dy * 3 + dx] * ip[yy * HW + xx];
        }
    }
    g_h2[((size_t)(b * 732 + c)) * NPIX + p] = acc;
}

// ---------------------------------------------------------------------------
// 8x8 circular convolution per patch:  o = irfft2(rfft2(q)*rfft2(k))
// q = g_h2[ch c], k = g_h2[ch 244+c]  ->  o into g_h (compact 244-ch layout)
// 4 patches per 256-thread block.
// ---------------------------------------------------------------------------
__global__ void circ8_kern()
{
    __shared__ float sq[4][64], sk[4][64];
    int pt = threadIdx.x >> 6;
    int t  = threadIdx.x & 63;
    long long pid = (long long)blockIdx.x * 4 + pt;
    int pb = (int)(pid & 1023);
    int bc = (int)(pid >> 10);          // b*244 + c
    int b = bc / 244, c = bc % 244;
    int py = pb >> 5, px = pb & 31;
    int row = t >> 3, col = t & 7;
    size_t qbase = ((size_t)(b * 732 + c)) * NPIX + (py * 8 + row) * HW + px * 8 + col;
    sq[pt][t] = g_h2[qbase];
    sk[pt][t] = g_h2[qbase + (size_t)244 * NPIX];
    __syncthreads();
    int m = row, n = col;
    float acc = 0.f;
#pragma unroll
    for (int i = 0; i < 8; ++i) {
        int km = (m - i) & 7;
#pragma unroll
        for (int j = 0; j < 8; ++j)
            acc += sq[pt][i * 8 + j] * sk[pt][km * 8 + ((n - j) & 7)];
    }
    g_h[((size_t)(b * 244 + c)) * NPIX + (py * 8 + m) * HW + px * 8 + n] = acc;
}

// ---------------------------------------------------------------------------
// LN over 244 channels of o (in g_h), scale by fnw/fnb, multiply by v (g_h2
// channels 488..731), in-place into g_h.
// ---------------------------------------------------------------------------
__global__ void ln2_mul_kern(const float* __restrict__ fnw, const float* __restrict__ fnb)
{
    int t = blockIdx.x * 256 + threadIdx.x;
    if (t >= 2 * NPIX) return;
    int b = t >> 16, p = t & (NPIX - 1);
    float* op = g_h + (size_t)b * 244 * NPIX + p;
    const float* vp = g_h2 + ((size_t)b * 732 + 488) * NPIX + p;
    float sum = 0.f, ss = 0.f;
    for (int c = 0; c < 244; ++c) {
        float v = op[(size_t)c * NPIX];
        sum += v; ss += v * v;
    }
    float mu  = sum * (1.f / 244.f);
    float var = ss * (1.f / 244.f) - mu * mu;
    float rs  = rsqrtf(var + 1e-5f);
    for (int c = 0; c < 244; ++c) {
        float v = op[(size_t)c * NPIX];
        float nrm = (v - mu) * rs * fnw[c] + fnb[c];
        op[(size_t)c * NPIX] = vp[(size_t)c * NPIX] * nrm;
    }
}

// ---------------------------------------------------------------------------
// SE: per (b,c) spatial mean of g_out, then tiny MLP -> g_se
// ---------------------------------------------------------------------------
__global__ void se_mean_kern()
{
    int c = blockIdx.x, b = blockIdx.y;
    const float* p = g_out + ((size_t)b * 122 + c) * NPIX;
    float s = 0.f;
    for (int i = threadIdx.x; i < NPIX; i += 256) s += p[i];
    __shared__ float red[256];
    red[threadIdx.x] = s;
    __syncthreads();
    for (int k = 128; k > 0; k >>= 1) {
        if (threadIdx.x < k) red[threadIdx.x] += red[threadIdx.x + k];
        __syncthreads();
    }
    if (threadIdx.x == 0) g_sey[b * 122 + c] = red[0] * (1.f / (float)NPIX);
}

__global__ void se_mlp_kern(const float* __restrict__ f1, const float* __restrict__ f2)
{
    int b = blockIdx.x;
    __shared__ float ym[122];
    __shared__ float y7[7];
    if (threadIdx.x < 122) ym[threadIdx.x] = g_sey[b * 122 + threadIdx.x];
    __syncthreads();
    if (threadIdx.x < 7) {
        float a = 0.f;
        for (int c = 0; c < 122; ++c) a += f1[threadIdx.x * 122 + c] * ym[c];
        y7[threadIdx.x] = fmaxf(a, 0.f);
    }
    __syncthreads();
    if (threadIdx.x < 122) {
        float a = 0.f;
#pragma unroll
        for (int j = 0; j < 7; ++j) a += f2[threadIdx.x * 7 + j] * y7[j];
        g_se[b * 122 + threadIdx.x] = 1.f / (1.f + expf(-a));
    }
}

// ---------------------------------------------------------------------------
// Soft threshold: z = soft(Wx, c * sigma)   (sigma broadcast over channels)
// ---------------------------------------------------------------------------
__global__ void soft_kern(const float* __restrict__ wx, const float* __restrict__ cth,
                          const float* __restrict__ sigma, float* __restrict__ z)
{
    size_t i = (size_t)blockIdx.x * 256 + threadIdx.x;
    if (i >= (size_t)2 * 121 * NPIX) return;
    int b = (int)(i / ((size_t)121 * NPIX));
    int p = (int)(i & (NPIX - 1));
    float t = cth[i] * sigma[b * NPIX + p];
    float x = wx[i];
    float r = 0.f;
    if (x > t) r = x - t;
    else if (x < -t) r = x + t;
    z[i] = r;
}

// ---------------------------------------------------------------------------
// Output init (w1 copy + zero loss), loss reduction, loss finalize
// ---------------------------------------------------------------------------
__global__ void init_out_kern(const float* __restrict__ w1, float* __restrict__ out)
{
    int i = blockIdx.x * 256 + threadIdx.x;
    if (i < 14641) out[131072 + i] = w1[i];
    if (i == 0) g_loss = 0.0;
}

__global__ void loss_kern()
{
    const size_t N = (size_t)2 * 121 * NPIX;
    double s = 0.0;
    for (size_t i = (size_t)blockIdx.x * 256 + threadIdx.x; i < N; i += (size_t)gridDim.x * 256) {
        float d = g_tA[i] - g_Wx1[i];
        s += (double)d * (double)d;
    }
    __shared__ double red[256];
    red[threadIdx.x] = s;
    __syncthreads();
    for (int k = 128; k > 0; k >>= 1) {
        if (threadIdx.x < k) red[threadIdx.x] += red[threadIdx.x + k];
        __syncthreads();
    }
    if (threadIdx.x == 0) atomicAdd(&g_loss, red[0]);
}

__global__ void loss_fin_kern(float* __restrict__ out)
{
    if (threadIdx.x == 0 && blockIdx.x == 0) out[145713] = (float)g_loss;
}

// ---------------------------------------------------------------------------
// Host orchestration (runs only during graph capture)
// ---------------------------------------------------------------------------
extern "C" void kernel_launch(void* const* d_in, const int* in_sizes, int n_in,
                              void* d_out, int out_size)
{
    const float* input = (const float*)d_in[0];
    const float* sigma = (const float*)d_in[1];
    const float* w1    = (const float*)d_in[2];
    const float* b1    = (const float*)d_in[3];
    const float* w2    = (const float*)d_in[4];
    const float* b2    = (const float*)d_in[5];
    const float* n1w   = (const float*)d_in[6];
    const float* n1b   = (const float*)d_in[7];
    const float* thw   = (const float*)d_in[8];
    const float* tdw   = (const float*)d_in[9];
    const float* fnw   = (const float*)d_in[10];
    const float* fnb   = (const float*)d_in[11];
    const float* pw    = (const float*)d_in[12];
    const float* s1a   = (const float*)d_in[13];
    const float* s1b   = (const float*)d_in[14];
    const float* s2a   = (const float*)d_in[15];
    const float* s2b   = (const float*)d_in[16];
    const float* c1w   = (const float*)d_in[17];
    const float* c1b   = (const float*)d_in[18];
    const float* c2w   = (const float*)d_in[19];
    const float* c2b   = (const float*)d_in[20];
    float* out = (float*)d_out;

    float *pWx1, *pWx2, *pZ, *pTA, *pTB, *pLn, *pH, *pCat, *pOut, *pWT2, *pWT1, *pSe;
    cudaGetSymbolAddress((void**)&pWx1, g_Wx1);
    cudaGetSymbolAddress((void**)&pWx2, g_Wx2);
    cudaGetSymbolAddress((void**)&pZ,   g_z);
    cudaGetSymbolAddress((void**)&pTA,  g_tA);
    cudaGetSymbolAddress((void**)&pTB,  g_tB);
    cudaGetSymbolAddress((void**)&pLn,  g_ln);
    cudaGetSymbolAddress((void**)&pH,   g_h);
    cudaGetSymbolAddress((void**)&pCat, g_cat);
    cudaGetSymbolAddress((void**)&pOut, g_out);
    cudaGetSymbolAddress((void**)&pWT2, g_wT2);
    cudaGetSymbolAddress((void**)&pWT1, g_wT1);
    cudaGetSymbolAddress((void**)&pSe,  g_se);

    const float inv121 = 1.f / 121.f;
    const dim3 blk(256);
    const dim3 gridC121(8, 8, 2 * 16);   // Cout=121 -> 16 co-groups of 8
    const dim3 gridC1(8, 8, 2 * 1);      // Cout=1
    const dim3 gridPix((2 * NPIX) / 256);

    prep_w_kern<<<2048, blk>>>(w1, w2);
    init_out_kern<<<58, blk>>>(w1, out);

    // Wx1 = conv11(rpad(input), w1) + b1
    convK_kern<11, true, false><<<gridC121, blk>>>(input, w1, b1, nullptr, pWx1, 1, 121, 1.f);

    for (int pass = 0; pass < 2; ++pass) {
        const float* wx  = (pass == 0) ? pWx1 : pWx2;
        const float* sea = (pass == 0) ? s1a : s2a;
        const float* seb = (pass == 0) ? s1b : s2b;
        const float* cw  = (pass == 0) ? c1w : c2w;
        const float* cb  = (pass == 0) ? c1b : c2b;

        // TransformerBlock (shared weights)
        ln_cat_kern<<<gridPix, blk>>>(input, wx, n1w, n1b);
        conv1x1_kern<false><<<dim3(256, 46, 2), blk>>>(pLn, thw, nullptr, pH, 122, 732);
        dwconv_kern<<<dim3(256, 732, 2), blk>>>(tdw);
        circ8_kern<<<124928, blk>>>();
        ln2_mul_kern<<<gridPix, blk>>>(fnw, fnb);
        conv1x1_kern<true><<<dim3(256, 8, 2), blk>>>(pH, pw, pCat, pOut, 244, 122);

        // SE -> c (3x3 conv, clip) -> soft threshold
        se_mean_kern<<<dim3(122, 2), blk>>>();
        se_mlp_kern<<<2, 128>>>(sea, seb);
        convK_kern<3, false, true><<<gridC121, blk>>>(pOut, cw, cb, pSe, pTA, 122, 121, 1.f);
        soft_kern<<<61952, blk>>>(wx, pTA, sigma, pZ);

        if (pass == 0) {
            // Wx2 = conv11(rpad(z1), w2) + b2
            convK_kern<11, true, false><<<gridC121, blk>>>(pZ, w2, b2, nullptr, pWx2, 121, 121, 1.f);
        }
    }

    // Wt2 = conv11(rpad(z2), wT2)/121 ; Wt = conv11(rpad(Wt2), wT1)/121
    convK_kern<11, true, false><<<gridC121, blk>>>(pZ, pWT2, nullptr, nullptr, pTA, 121, 121, inv121);
    convK_kern<11, true, false><<<gridC1, blk>>>(pTA, pWT1, nullptr, nullptr, out, 121, 1, inv121);

    // temp = conv11(rpad(Wx1), w2)+b2 ; WTW2 = conv11(rpad(temp), wT2)/121 ; loss
    convK_kern<11, true, false><<<gridC121, blk>>>(pWx1, w2, b2, nullptr, pTB, 121, 121, 1.f);
    convK_kern<11, true, false><<<gridC121, blk>>>(pTB, pWT2, nullptr, nullptr, pTA, 121, 121, inv121);
    loss_kern<<<1024, blk>>>();
    loss_fin_kern<<<1, 32>>>(out);
}

// round 11
// speedup vs baseline: 2.2668x; 1.8451x over previous
#include <cuda_runtime.h>
#include <cuda_bf16.h>

#define NPIX 65536
#define HW 256
#define NFRAG (121*8*8*32*4)   // tap, cichunk, coatom, lane, word

__device__ float g_Wx1[2 * 121 * NPIX];
__device__ float g_Wx2[2 * 121 * NPIX];
__device__ float g_z  [2 * 121 * NPIX];
__device__ float g_tA [2 * 121 * NPIX];
__device__ float g_tB [2 * 121 * NPIX];
__device__ float g_cat[2 * 122 * NPIX];
__device__ float g_ln [2 * 122 * NPIX];
__device__ float g_out[2 * 122 * NPIX];
__device__ float g_h  [2 * 732 * NPIX];
__device__ float g_h2 [2 * 732 * NPIX];
__device__ float g_wT1[121 * 121];
__device__ float g_sey[2 * 122];
__device__ float g_se [2 * 122];
__device__ double g_loss;
__device__ unsigned int g_fw2h[NFRAG], g_fw2l[NFRAG];
__device__ unsigned int g_fwT2h[NFRAG], g_fwT2l[NFRAG];

__device__ __forceinline__ int refl(int i) {
    i = (i < 0) ? -i : i;
    return (i < HW) ? i : (2 * HW - 2 - i);
}
__device__ __forceinline__ unsigned long long pack2(float lo, float hi) {
    unsigned long long r;
    asm("mov.b64 %0, {%1, %2};" : "=l"(r) : "f"(lo), "f"(hi));
    return r;
}
__device__ __forceinline__ void fma2(unsigned long long& a, unsigned long long w,
                                     unsigned long long v) {
    asm("fma.rn.f32x2 %0, %1, %2, %0;" : "+l"(a) : "l"(w), "l"(v));
}
__device__ __forceinline__ void unpack2(unsigned long long v, float& lo, float& hi) {
    asm("mov.b64 {%0, %1}, %2;" : "=f"(lo), "=f"(hi) : "l"(v));
}
__device__ __forceinline__ void mma_bf16(float* c, uint4 a, unsigned int b0, unsigned int b1) {
    asm volatile("mma.sync.aligned.m16n8k16.row.col.f32.bf16.bf16.f32 "
                 "{%0,%1,%2,%3},{%4,%5,%6,%7},{%8,%9},{%0,%1,%2,%3};"
                 : "+f"(c[0]), "+f"(c[1]), "+f"(c[2]), "+f"(c[3])
                 : "r"(a.x), "r"(a.y), "r"(a.z), "r"(a.w), "r"(b0), "r"(b1));
}

// wT1[ci][tap] = w1[ci][120-tap]
__global__ void prep_w_kern(const float* __restrict__ w1)
{
    int i = blockIdx.x * 256 + threadIdx.x;
    if (i < 121 * 121) {
        int ci = i / 121, tap = i % 121;
        g_wT1[ci * 121 + tap] = w1[ci * 121 + (120 - tap)];
    }
}

// Pre-fragment w2 and wT2 into mma A-fragments (hi/lo bf16 split).
// idx = (((tap*8+cc)*8+atom)*32+lane)*4+j ; word j: j&1 -> row+8, j>=2 -> k+8
__global__ void prep_frag_kern(const float* __restrict__ w2)
{
    for (int idx = blockIdx.x * 256 + threadIdx.x; idx < NFRAG; idx += gridDim.x * 256) {
        int j    = idx & 3;
        int lane = (idx >> 2) & 31;
        int atom = (idx >> 7) & 7;
        int cc   = (idx >> 10) & 7;
        int tap  = idx >> 13;
        int co = atom * 16 + (lane >> 2) + ((j & 1) ? 8 : 0);
        int k0 = (lane & 3) * 2 + ((j >= 2) ? 8 : 0);
        float a[2], t[2];
#pragma unroll
        for (int e = 0; e < 2; ++e) {
            int ci = cc * 16 + k0 + e;
            bool ok = (co < 121) && (ci < 121);
            a[e] = ok ? w2[((size_t)co * 121 + ci) * 121 + tap] : 0.f;
            t[e] = ok ? w2[((size_t)ci * 121 + co) * 121 + (120 - tap)] : 0.f;
        }
        unsigned int h, l;
        {
            __nv_bfloat16 h0 = __float2bfloat16_rn(a[0]), h1 = __float2bfloat16_rn(a[1]);
            float l0 = a[0] - __bfloat162float(h0), l1 = a[1] - __bfloat162float(h1);
            h = (unsigned)__bfloat16_as_ushort(h0) | ((unsigned)__bfloat16_as_ushort(h1) << 16);
            l = (unsigned)__bfloat16_as_ushort(__float2bfloat16_rn(l0)) |
                ((unsigned)__bfloat16_as_ushort(__float2bfloat16_rn(l1)) << 16);
        }
        g_fw2h[idx] = h; g_fw2l[idx] = l;
        {
            __nv_bfloat16 h0 = __float2bfloat16_rn(t[0]), h1 = __float2bfloat16_rn(t[1]);
            float l0 = t[0] - __bfloat162float(h0), l1 = t[1] - __bfloat162float(h1);
            h = (unsigned)__bfloat16_as_ushort(h0) | ((unsigned)__bfloat16_as_ushort(h1) << 16);
            l = (unsigned)__bfloat16_as_ushort(__float2bfloat16_rn(l0)) |
                ((unsigned)__bfloat16_as_ushort(__float2bfloat16_rn(l1)) << 16);
        }
        g_fwT2h[idx] = h; g_fwT2l[idx] = l;
    }
}

// ---------------------------------------------------------------------------
// Tensor 11x11 reflect conv, 121ch -> 121ch, as 121 tap-GEMMs via mma.sync.
// Block: 128 px (half row y) x 128 co. Warp: co-half (4 m-atoms) x px-quarter
// (4 n-atoms). Input staged per (ci-chunk 16, dy) as bf16-pair uint2:
// slot s holds ci-pairs {s, s+4} -> one LDS.64 = full B k-column.
// ---------------------------------------------------------------------------
#define SPX 144
__global__ void __launch_bounds__(256) convT_kern(
    const float* __restrict__ in, const unsigned int* __restrict__ wh,
    const unsigned int* __restrict__ wl, const float* __restrict__ bias,
    float* __restrict__ out, float outscale)
{
    __shared__ uint2 s_bh[SPX * 4], s_bl[SPX * 4];
    const int x0 = blockIdx.x * 128, y = blockIdx.y, b = blockIdx.z;
    const int tid = threadIdx.x, w = tid >> 5, lane = tid & 31;
    const int ch = w & 1;        // co half
    const int pq = w >> 1;       // px quarter
    const int lr = lane >> 2, lc = lane & 3;

    float acc[4][4][4];
#pragma unroll
    for (int m = 0; m < 4; ++m)
#pragma unroll
        for (int n = 0; n < 4; ++n)
#pragma unroll
            for (int q = 0; q < 4; ++q) acc[m][n][q] = 0.f;

    const size_t inB = (size_t)b * 121 * NPIX;

    for (int cc = 0; cc < 8; ++cc) {
        for (int dy = 0; dy < 11; ++dy) {
            __syncthreads();
            const int gy = refl(y + dy - 5);
            for (int t = tid; t < 16 * 138; t += 256) {
                int ci = t / 138, px = t - ci * 138;
                int cig = cc * 16 + ci;
                float v = 0.f;
                if (cig < 121)
                    v = in[inB + (size_t)cig * NPIX + gy * HW + refl(x0 + px - 5)];
                unsigned hv = __float_as_uint(v) & 0xFFFF0000u;
                float lo = v - __uint_as_float(hv);
                unsigned short ls = __bfloat16_as_ushort(__float2bfloat16_rn(lo));
                int p = ci >> 1;
                int off = (px * 4 + (p & 3)) * 8 + ((p >> 2) << 2) + ((ci & 1) << 1);
                *(unsigned short*)((char*)s_bh + off) = (unsigned short)(hv >> 16);
                *(unsigned short*)((char*)s_bl + off) = ls;
            }
            __syncthreads();
#pragma unroll 1
            for (int dx = 0; dx < 11; ++dx) {
                const int tap = dy * 11 + dx;
                uint4 ah[4], al[4];
#pragma unroll
                for (int m = 0; m < 4; ++m) {
                    size_t o = (((size_t)(tap * 8 + cc) * 8 + (ch * 4 + m)) << 7) + lane * 4;
                    ah[m] = *(const uint4*)(wh + o);
                    al[m] = *(const uint4*)(wl + o);
                }
                uint2 bh[4], bl[4];
#pragma unroll
                for (int n = 0; n < 4; ++n) {
                    int px = pq * 32 + n * 8 + lr + dx;
                    bh[n] = s_bh[px * 4 + lc];
                    bl[n] = s_bl[px * 4 + lc];
                }
#pragma unroll
                for (int m = 0; m < 4; ++m)
#pragma unroll
                    for (int n = 0; n < 4; ++n)
                        mma_bf16(acc[m][n], ah[m], bh[n].x, bh[n].y);
#pragma unroll
                for (int m = 0; m < 4; ++m)
#pragma unroll
                    for (int n = 0; n < 4; ++n)
                        mma_bf16(acc[m][n], al[m], bh[n].x, bh[n].y);
#pragma unroll
                for (int m = 0; m < 4; ++m)
#pragma unroll
                    for (int n = 0; n < 4; ++n)
                        mma_bf16(acc[m][n], ah[m], bl[n].x, bl[n].y);
            }
        }
    }

    const size_t outB = (size_t)b * 121 * NPIX + (size_t)y * HW;
#pragma unroll
    for (int m = 0; m < 4; ++m) {
#pragma unroll
        for (int hh = 0; hh < 2; ++hh) {
            int co = (ch * 4 + m) * 16 + lr + hh * 8;
            if (co >= 121) continue;
            float bv = bias ? bias[co] : 0.f;
#pragma unroll
            for (int n = 0; n < 4; ++n) {
                int px = x0 + pq * 32 + n * 8 + lc * 2;
                float2 v;
                v.x = acc[m][n][hh * 2 + 0] * outscale + bv;
                v.y = acc[m][n][hh * 2 + 1] * outscale + bv;
                *(float2*)(out + outB + (size_t)co * NPIX + px) = v;
            }
        }
    }
}

// ---------------------------------------------------------------------------
// Scalar KSxKS conv (FFMA2) — Wx1 (Cin=1), final Wt (Cout=1), 3x3 SE convs.
// ---------------------------------------------------------------------------
template<int KS, bool REFLECT, bool CLIP>
__global__ void __launch_bounds__(256) convK_kern(
    const float* __restrict__ in, const float* __restrict__ wbuf,
    const float* __restrict__ bias, const float* __restrict__ chscale,
    float* __restrict__ out, int Cin, int Cout, float outscale)
{
    constexpr int PAD = KS / 2;
    constexpr int IN  = 32 + KS - 1;
    constexpr int STR = IN + 1;
    constexpr int KK  = KS * KS;
    __shared__ __align__(16) float s_w8[KK * 8];
    __shared__ float s_in[IN * STR];

    const int nCoG = (Cout + 7) >> 3;
    const int b    = blockIdx.z / nCoG;
    const int cog  = blockIdx.z % nCoG;
    const int by = blockIdx.y, bx = blockIdx.x;
    const int tid = threadIdx.x;
    const int ty = tid >> 4, tx = tid & 15;
    const int r0 = ty * 2, c0 = tx * 2;

    unsigned long long acc2[4][4];
#pragma unroll
    for (int p = 0; p < 4; ++p)
#pragma unroll
        for (int q = 0; q < 4; ++q) acc2[p][q] = 0ull;

    const size_t inBase  = (size_t)b * Cin * NPIX;
    const int    co0     = cog * 8;
    const size_t wstride = (size_t)Cin * KK;

    for (int ci = 0; ci < Cin; ++ci) {
        const float* ip = in + inBase + (size_t)ci * NPIX;
        float sc = 1.f;
        if (chscale) sc = chscale[b * Cin + ci];
        for (int idx = tid; idx < IN * IN; idx += 256) {
            int row = idx / IN, col = idx - row * IN;
            int gy = by * 32 + row - PAD;
            int gx = bx * 32 + col - PAD;
            float v;
            if (REFLECT) v = ip[refl(gy) * HW + refl(gx)];
            else v = (gy >= 0 && gy < HW && gx >= 0 && gx < HW) ? ip[gy * HW + gx] : 0.f;
            s_in[row * STR + col] = v * sc;
        }
        {
            const float* wci = wbuf + (size_t)ci * KK;
            for (int t = tid; t < KK * 8; t += 256) {
                int tap = t >> 3, j = t & 7;
                int co  = co0 + j;
                int cosafe = (co < Cout) ? co : (Cout - 1);
                float wv = wci[(size_t)cosafe * wstride + tap];
                s_w8[t] = (co < Cout) ? wv : 0.f;
            }
        }
        __syncthreads();
#pragma unroll 1
        for (int r = 0; r < KS; ++r) {
            const float* p0 = &s_in[(r0 + r) * STR + c0];
            const float* p1 = p0 + STR;
#pragma unroll
            for (int s = 0; s < KS; ++s) {
                const unsigned long long* wq =
                    (const unsigned long long*)&s_w8[(r * KS + s) * 8];
                unsigned long long w01 = wq[0], w23 = wq[1];
                unsigned long long w45 = wq[2], w67 = wq[3];
                unsigned long long v00 = pack2(p0[s], p0[s]);
                unsigned long long v01 = pack2(p0[s + 1], p0[s + 1]);
                unsigned long long v10 = pack2(p1[s], p1[s]);
                unsigned long long v11 = pack2(p1[s + 1], p1[s + 1]);
                fma2(acc2[0][0], w01, v00); fma2(acc2[0][1], w23, v00);
                fma2(acc2[0][2], w45, v00); fma2(acc2[0][3], w67, v00);
                fma2(acc2[1][0], w01, v01); fma2(acc2[1][1], w23, v01);
                fma2(acc2[1][2], w45, v01); fma2(acc2[1][3], w67, v01);
                fma2(acc2[2][0], w01, v10); fma2(acc2[2][1], w23, v10);
                fma2(acc2[2][2], w45, v10); fma2(acc2[2][3], w67, v10);
                fma2(acc2[3][0], w01, v11); fma2(acc2[3][1], w23, v11);
                fma2(acc2[3][2], w45, v11); fma2(acc2[3][3], w67, v11);
            }
        }
        __syncthreads();
    }

    float acc[4][8];
#pragma unroll
    for (int p = 0; p < 4; ++p)
#pragma unroll
        for (int q = 0; q < 4; ++q)
            unpack2(acc2[p][q], acc[p][2 * q], acc[p][2 * q + 1]);

    const int oy = by * 32 + r0, ox = bx * 32 + c0;
    const size_t outBase = (size_t)b * Cout * NPIX;
#pragma unroll
    for (int j = 0; j < 8; ++j) {
        int co = co0 + j;
        if (co >= Cout) break;
        float bv = bias ? bias[co] : 0.f;
        float* op = out + outBase + (size_t)co * NPIX;
        float r00 = acc[0][j] * outscale + bv;
        float r01 = acc[1][j] * outscale + bv;
        float r10 = acc[2][j] * outscale + bv;
        float r11 = acc[3][j] * outscale + bv;
        if (CLIP) {
            r00 = fminf(fmaxf(r00, 0.f), 10.f);
            r01 = fminf(fmaxf(r01, 0.f), 10.f);
            r10 = fminf(fmaxf(r10, 0.f), 10.f);
            r11 = fminf(fmaxf(r11, 0.f), 10.f);
        }
        op[oy * HW + ox]           = r00;
        op[oy * HW + ox + 1]       = r01;
        op[(oy + 1) * HW + ox]     = r10;
        op[(oy + 1) * HW + ox + 1] = r11;
    }
}

template<bool RESID>
__global__ void __launch_bounds__(256) conv1x1_kern(
    const float* __restrict__ x, const float* __restrict__ w,
    const float* __restrict__ resid, float* __restrict__ out,
    int Cin, int Cout)
{
    __shared__ float4 s_w[244 * 4];
    const int b   = blockIdx.z;
    const int co0 = blockIdx.y * 16;
    const int px  = blockIdx.x * 256 + threadIdx.x;
    for (int t = threadIdx.x; t < Cin * 4; t += 256) {
        int ci = t >> 2, g = t & 3;
        int co = co0 + g * 4;
        float4 v;
        v.x = (co + 0 < Cout) ? w[(size_t)(co + 0) * Cin + ci] : 0.f;
        v.y = (co + 1 < Cout) ? w[(size_t)(co + 1) * Cin + ci] : 0.f;
        v.z = (co + 2 < Cout) ? w[(size_t)(co + 2) * Cin + ci] : 0.f;
        v.w = (co + 3 < Cout) ? w[(size_t)(co + 3) * Cin + ci] : 0.f;
        s_w[t] = v;
    }
    __syncthreads();
    float acc[16];
#pragma unroll
    for (int j = 0; j < 16; ++j) acc[j] = 0.f;
    const float* xp = x + (size_t)b * Cin * NPIX + px;
#pragma unroll 2
    for (int ci = 0; ci < Cin; ++ci) {
        float xv = xp[(size_t)ci * NPIX];
#pragma unroll
        for (int g = 0; g < 4; ++g) {
            float4 w4 = s_w[ci * 4 + g];
            acc[g * 4 + 0] += w4.x * xv;
            acc[g * 4 + 1] += w4.y * xv;
            acc[g * 4 + 2] += w4.z * xv;
            acc[g * 4 + 3] += w4.w * xv;
        }
    }
    const size_t ob = (size_t)b * Cout * NPIX + px;
#pragma unroll
    for (int j = 0; j < 16; ++j) {
        int co = co0 + j;
        if (co < Cout) {
            float v = acc[j];
            if (RESID) v += resid[ob + (size_t)co * NPIX];
            out[ob + (size_t)co * NPIX] = v;
        }
    }
}

__global__ void ln_cat_kern(const float* __restrict__ in0, const float* __restrict__ wx,
                            const float* __restrict__ gw, const float* __restrict__ gb)
{
    int t = blockIdx.x * 256 + threadIdx.x;
    if (t >= 2 * NPIX) return;
    int b = t >> 16, p = t & (NPIX - 1);
    float x0 = in0[t];
    const float* wp = wx + (size_t)b * 121 * NPIX + p;
    float sum = x0, ss = x0 * x0;
    for (int c = 0; c < 121; ++c) {
        float v = wp[(size_t)c * NPIX];
        sum += v; ss += v * v;
    }
    float mu  = sum * (1.f / 122.f);
    float var = ss * (1.f / 122.f) - mu * mu;
    float rs  = rsqrtf(var + 1e-5f);
    size_t base = (size_t)b * 122 * NPIX + p;
    g_cat[base] = x0;
    g_ln[base]  = (x0 - mu) * rs * gw[0] + gb[0];
    for (int c = 0; c < 121; ++c) {
        float v = wp[(size_t)c * NPIX];
        g_cat[base + (size_t)(c + 1) * NPIX] = v;
        g_ln[base + (size_t)(c + 1) * NPIX]  = (v - mu) * rs * gw[c + 1] + gb[c + 1];
    }
}

__global__ void dwconv_kern(const float* __restrict__ w)
{
    int c = blockIdx.y, b = blockIdx.z;
    int p = blockIdx.x * 256 + threadIdx.x;
    int y = p >> 8, x = p & 255;
    const float* ip = g_h + ((size_t)(b * 732 + c)) * NPIX;
    float wv[9];
#pragma unroll
    for (int i = 0; i < 9; ++i) wv[i] = w[c * 9 + i];
    float acc = 0.f;
#pragma unroll
    for (int dy = 0; dy < 3; ++dy) {
        int yy = y + dy - 1;
        if (yy < 0 || yy > 255) continue;
#pragma unroll
        for (int dx = 0; dx < 3; ++dx) {
            int xx = x + dx - 1;
            if (xx < 0 || xx > 255) continue;
            acc += wv[dy * 3 + dx] * ip[yy * HW + xx];
        }
    }
    g_h2[((size_t)(b * 732 + c)) * NPIX + p] = acc;
}

__global__ void circ8_kern()
{
    __shared__ float sq[4][64], sk[4][64];
    int pt = threadIdx.x >> 6;
    int t  = threadIdx.x & 63;
    long long pid = (long long)blockIdx.x * 4 + pt;
    int pb = (int)(pid & 1023);
    int bc = (int)(pid >> 10);
    int b = bc / 244, c = bc % 244;
    int py = pb >> 5, px = pb & 31;
    int row = t >> 3, col = t & 7;
    size_t qbase = ((size_t)(b * 732 + c)) * NPIX + (py * 8 + row) * HW + px * 8 + col;
    sq[pt][t] = g_h2[qbase];
    sk[pt][t] = g_h2[qbase + (size_t)244 * NPIX];
    __syncthreads();
    int m = row, n = col;
    float acc = 0.f;
#pragma unroll
    for (int i = 0; i < 8; ++i) {
        int km = (m - i) & 7;
#pragma unroll
        for (int j = 0; j < 8; ++j)
            acc += sq[pt][i * 8 + j] * sk[pt][km * 8 + ((n - j) & 7)];
    }
    g_h[((size_t)(b * 244 + c)) * NPIX + (py * 8 + m) * HW + px * 8 + n] = acc;
}

__global__ void ln2_mul_kern(const float* __restrict__ fnw, const float* __restrict__ fnb)
{
    int t = blockIdx.x * 256 + threadIdx.x;
    if (t >= 2 * NPIX) return;
    int b = t >> 16, p = t & (NPIX - 1);
    float* op = g_h + (size_t)b * 244 * NPIX + p;
    const float* vp = g_h2 + ((size_t)b * 732 + 488) * NPIX + p;
    float sum = 0.f, ss = 0.f;
    for (int c = 0; c < 244; ++c) {
        float v = op[(size_t)c * NPIX];
        sum += v; ss += v * v;
    }
    float mu  = sum * (1.f / 244.f);
    float var = ss * (1.f / 244.f) - mu * mu;
    float rs  = rsqrtf(var + 1e-5f);
    for (int c = 0; c < 244; ++c) {
        float v = op[(size_t)c * NPIX];
        float nrm = (v - mu) * rs * fnw[c] + fnb[c];
        op[(size_t)c * NPIX] = vp[(size_t)c * NPIX] * nrm;
    }
}

__global__ void se_mean_kern()
{
    int c = blockIdx.x, b = blockIdx.y;
    const float* p = g_out + ((size_t)b * 122 + c) * NPIX;
    float s = 0.f;
    for (int i = threadIdx.x; i < NPIX; i += 256) s += p[i];
    __shared__ float red[256];
    red[threadIdx.x] = s;
    __syncthreads();
    for (int k = 128; k > 0; k >>= 1) {
        if (threadIdx.x < k) red[threadIdx.x] += red[threadIdx.x + k];
        __syncthreads();
    }
    if (threadIdx.x == 0) g_sey[b * 122 + c] = red[0] * (1.f / (float)NPIX);
}

__global__ void se_mlp_kern(const float* __restrict__ f1, const float* __restrict__ f2)
{
    int b = blockIdx.x;
    __shared__ float ym[122];
    __shared__ float y7[7];
    if (threadIdx.x < 122) ym[threadIdx.x] = g_sey[b * 122 + threadIdx.x];
    __syncthreads();
    if (threadIdx.x < 7) {
        float a = 0.f;
        for (int c = 0; c < 122; ++c) a += f1[threadIdx.x * 122 + c] * ym[c];
        y7[threadIdx.x] = fmaxf(a, 0.f);
    }
    __syncthreads();
    if (threadIdx.x < 122) {
        float a = 0.f;
#pragma unroll
        for (int j = 0; j < 7; ++j) a += f2[threadIdx.x * 7 + j] * y7[j];
        g_se[b * 122 + threadIdx.x] = 1.f / (1.f + expf(-a));
    }
}

__global__ void soft_kern(const float* __restrict__ wx, const float* __restrict__ cth,
                          const float* __restrict__ sigma, float* __restrict__ z)
{
    size_t i = (size_t)blockIdx.x * 256 + threadIdx.x;
    if (i >= (size_t)2 * 121 * NPIX) return;
    int b = (int)(i / ((size_t)121 * NPIX));
    int p = (int)(i & (NPIX - 1));
    float t = cth[i] * sigma[b * NPIX + p];
    float x = wx[i];
    float r = 0.f;
    if (x > t) r = x - t;
    else if (x < -t) r = x + t;
    z[i] = r;
}

__global__ void init_out_kern(const float* __restrict__ w1, float* __restrict__ out)
{
    int i = blockIdx.x * 256 + threadIdx.x;
    if (i < 14641) out[131072 + i] = w1[i];
    if (i == 0) g_loss = 0.0;
}

__global__ void loss_kern()
{
    const size_t N = (size_t)2 * 121 * NPIX;
    double s = 0.0;
    for (size_t i = (size_t)blockIdx.x * 256 + threadIdx.x; i < N; i += (size_t)gridDim.x * 256) {
        float d = g_tA[i] - g_Wx1[i];
        s += (double)d * (double)d;
    }
    __shared__ double red[256];
    red[threadIdx.x] = s;
    __syncthreads();
    for (int k = 128; k > 0; k >>= 1) {
        if (threadIdx.x < k) red[threadIdx.x] += red[threadIdx.x + k];
        __syncthreads();
    }
    if (threadIdx.x == 0) atomicAdd(&g_loss, red[0]);
}

__global__ void loss_fin_kern(float* __restrict__ out)
{
    if (threadIdx.x == 0 && blockIdx.x == 0) out[145713] = (float)g_loss;
}

extern "C" void kernel_launch(void* const* d_in, const int* in_sizes, int n_in,
                              void* d_out, int out_size)
{
    const float* input = (const float*)d_in[0];
    const float* sigma = (const float*)d_in[1];
    const float* w1    = (const float*)d_in[2];
    const float* b1    = (const float*)d_in[3];
    const float* w2    = (const float*)d_in[4];
    const float* b2    = (const float*)d_in[5];
    const float* n1w   = (const float*)d_in[6];
    const float* n1b   = (const float*)d_in[7];
    const float* thw   = (const float*)d_in[8];
    const float* tdw   = (const float*)d_in[9];
    const float* fnw   = (const float*)d_in[10];
    const float* fnb   = (const float*)d_in[11];
    const float* pw    = (const float*)d_in[12];
    const float* s1a   = (const float*)d_in[13];
    const float* s1b   = (const float*)d_in[14];
    const float* s2a   = (const float*)d_in[15];
    const float* s2b   = (const float*)d_in[16];
    const float* c1w   = (const float*)d_in[17];
    const float* c1b   = (const float*)d_in[18];
    const float* c2w   = (const float*)d_in[19];
    const float* c2b   = (const float*)d_in[20];
    float* out = (float*)d_out;

    float *pWx1, *pWx2, *pZ, *pTA, *pTB, *pLn, *pH, *pCat, *pOut, *pWT1, *pSe;
    unsigned int *pF2h, *pF2l, *pFTh, *pFTl;
    cudaGetSymbolAddress((void**)&pWx1, g_Wx1);
    cudaGetSymbolAddress((void**)&pWx2, g_Wx2);
    cudaGetSymbolAddress((void**)&pZ,   g_z);
    cudaGetSymbolAddress((void**)&pTA,  g_tA);
    cudaGetSymbolAddress((void**)&pTB,  g_tB);
    cudaGetSymbolAddress((void**)&pLn,  g_ln);
    cudaGetSymbolAddress((void**)&pH,   g_h);
    cudaGetSymbolAddress((void**)&pCat, g_cat);
    cudaGetSymbolAddress((void**)&pOut, g_out);
    cudaGetSymbolAddress((void**)&pWT1, g_wT1);
    cudaGetSymbolAddress((void**)&pSe,  g_se);
    cudaGetSymbolAddress((void**)&pF2h, g_fw2h);
    cudaGetSymbolAddress((void**)&pF2l, g_fw2l);
    cudaGetSymbolAddress((void**)&pFTh, g_fwT2h);
    cudaGetSymbolAddress((void**)&pFTl, g_fwT2l);

    const float inv121 = 1.f / 121.f;
    const dim3 blk(256);
    const dim3 gridC121(8, 8, 2 * 16);
    const dim3 gridC1(8, 8, 2 * 1);
    const dim3 gridT(2, 256, 2);
    const dim3 gridPix((2 * NPIX) / 256);

    prep_w_kern<<<58, blk>>>(w1);
    prep_frag_kern<<<2048, blk>>>(w2);
    init_out_kern<<<58, blk>>>(w1, out);

    convK_kern<11, true, false><<<gridC121, blk>>>(input, w1, b1, nullptr, pWx1, 1, 121, 1.f);

    for (int pass = 0; pass < 2; ++pass) {
        const float* wx  = (pass == 0) ? pWx1 : pWx2;
        const float* sea = (pass == 0) ? s1a : s2a;
        const float* seb = (pass == 0) ? s1b : s2b;
        const float* cw  = (pass == 0) ? c1w : c2w;
        const float* cb  = (pass == 0) ? c1b : c2b;

        ln_cat_kern<<<gridPix, blk>>>(input, wx, n1w, n1b);
        conv1x1_kern<false><<<dim3(256, 46, 2), blk>>>(pLn, thw, nullptr, pH, 122, 732);
        dwconv_kern<<<dim3(256, 732, 2), blk>>>(tdw);
        circ8_kern<<<124928, blk>>>();
        ln2_mul_kern<<<gridPix, blk>>>(fnw, fnb);
        conv1x1_kern<true><<<dim3(256, 8, 2), blk>>>(pH, pw, pCat, pOut, 244, 122);

        se_mean_kern<<<dim3(122, 2), blk>>>();
        se_mlp_kern<<<2, 128>>>(sea, seb);
        convK_kern<3, false, true><<<gridC121, blk>>>(pOut, cw, cb, pSe, pTA, 122, 121, 1.f);
        soft_kern<<<61952, blk>>>(wx, pTA, sigma, pZ);

        if (pass == 0)
            convT_kern<<<gridT, blk>>>(pZ, pF2h, pF2l, b2, pWx2, 1.f);
    }

    // Wt2 = convT(z2, wT2)/121 ; Wt = scalar conv(wT1)/121
    convT_kern<<<gridT, blk>>>(pZ, pFTh, pFTl, nullptr, pTA, inv121);
    convK_kern<11, true, false><<<gridC1, blk>>>(pTA, pWT1, nullptr, nullptr, out, 121, 1, inv121);

    // temp = convT(Wx1, w2)+b2 ; WTW2 = convT(temp, wT2)/121 ; loss
    convT_kern<<<gridT, blk>>>(pWx1, pF2h, pF2l, b2, pTB, 1.f);
    convT_kern<<<gridT, blk>>>(pTB, pFTh, pFTl, nullptr, pTA, inv121);
    loss_kern<<<1024, blk>>>();
    loss_fin_kern<<<1, 32>>>(out);
}

// round 12
// speedup vs baseline: 2.2903x; 1.0104x over previous
#include <cuda_runtime.h>
#include <cuda_bf16.h>

#define NPIX 65536
#define HW 256
#define NFRAG (121*8*8*32*4)   // tap, cichunk, coatom, lane, word

__device__ float g_Wx1[2 * 121 * NPIX];
__device__ float g_Wx2[2 * 121 * NPIX];
__device__ float g_z  [2 * 121 * NPIX];
__device__ float g_tA [2 * 121 * NPIX];
__device__ float g_tB [2 * 121 * NPIX];
__device__ float g_tC [2 * 121 * NPIX];
__device__ float g_cat[2 * 122 * NPIX];
__device__ float g_ln [2 * 122 * NPIX];
__device__ float g_out[2 * 122 * NPIX];
__device__ float g_h  [2 * 732 * NPIX];
__device__ float g_h2 [2 * 732 * NPIX];
__device__ float g_wT1[121 * 121];
__device__ float g_sey[2 * 122];
__device__ float g_se [2 * 122];
__device__ double g_loss;
__device__ unsigned int g_fw2h[NFRAG], g_fw2l[NFRAG];
__device__ unsigned int g_fwT2h[NFRAG], g_fwT2l[NFRAG];

__device__ __forceinline__ int refl(int i) {
    i = (i < 0) ? -i : i;
    return (i < HW) ? i : (2 * HW - 2 - i);
}
__device__ __forceinline__ unsigned long long pack2(float lo, float hi) {
    unsigned long long r;
    asm("mov.b64 %0, {%1, %2};" : "=l"(r) : "f"(lo), "f"(hi));
    return r;
}
__device__ __forceinline__ void fma2(unsigned long long& a, unsigned long long w,
                                     unsigned long long v) {
    asm("fma.rn.f32x2 %0, %1, %2, %0;" : "+l"(a) : "l"(w), "l"(v));
}
__device__ __forceinline__ void unpack2(unsigned long long v, float& lo, float& hi) {
    asm("mov.b64 {%0, %1}, %2;" : "=f"(lo), "=f"(hi) : "l"(v));
}
__device__ __forceinline__ void mma_bf16(float* c, uint4 a, unsigned int b0, unsigned int b1) {
    asm volatile("mma.sync.aligned.m16n8k16.row.col.f32.bf16.bf16.f32 "
                 "{%0,%1,%2,%3},{%4,%5,%6,%7},{%8,%9},{%0,%1,%2,%3};"
                 : "+f"(c[0]), "+f"(c[1]), "+f"(c[2]), "+f"(c[3])
                 : "r"(a.x), "r"(a.y), "r"(a.z), "r"(a.w), "r"(b0), "r"(b1));
}

// wT1[ci][tap] = w1[ci][120-tap]
__global__ void prep_w_kern(const float* __restrict__ w1)
{
    int i = blockIdx.x * 256 + threadIdx.x;
    if (i < 121 * 121) {
        int ci = i / 121, tap = i % 121;
        g_wT1[ci * 121 + tap] = w1[ci * 121 + (120 - tap)];
    }
}

// Pre-fragment w2 and wT2 into mma A-fragments (hi/lo bf16 split).
// idx = (((tap*8+cc)*8+atom)*32+lane)*4+j ; word j: j&1 -> row+8, j>=2 -> k+8
__global__ void prep_frag_kern(const float* __restrict__ w2)
{
    for (int idx = blockIdx.x * 256 + threadIdx.x; idx < NFRAG; idx += gridDim.x * 256) {
        int j    = idx & 3;
        int lane = (idx >> 2) & 31;
        int atom = (idx >> 7) & 7;
        int cc   = (idx >> 10) & 7;
        int tap  = idx >> 13;
        int co = atom * 16 + (lane >> 2) + ((j & 1) ? 8 : 0);
        int k0 = (lane & 3) * 2 + ((j >= 2) ? 8 : 0);
        float a[2], t[2];
#pragma unroll
        for (int e = 0; e < 2; ++e) {
            int ci = cc * 16 + k0 + e;
            bool ok = (co < 121) && (ci < 121);
            a[e] = ok ? w2[((size_t)co * 121 + ci) * 121 + tap] : 0.f;
            t[e] = ok ? w2[((size_t)ci * 121 + co) * 121 + (120 - tap)] : 0.f;
        }
        unsigned int h, l;
        {
            __nv_bfloat16 h0 = __float2bfloat16_rn(a[0]), h1 = __float2bfloat16_rn(a[1]);
            float l0 = a[0] - __bfloat162float(h0), l1 = a[1] - __bfloat162float(h1);
            h = (unsigned)__bfloat16_as_ushort(h0) | ((unsigned)__bfloat16_as_ushort(h1) << 16);
            l = (unsigned)__bfloat16_as_ushort(__float2bfloat16_rn(l0)) |
                ((unsigned)__bfloat16_as_ushort(__float2bfloat16_rn(l1)) << 16);
        }
        g_fw2h[idx] = h; g_fw2l[idx] = l;
        {
            __nv_bfloat16 h0 = __float2bfloat16_rn(t[0]), h1 = __float2bfloat16_rn(t[1]);
            float l0 = t[0] - __bfloat162float(h0), l1 = t[1] - __bfloat162float(h1);
            h = (unsigned)__bfloat16_as_ushort(h0) | ((unsigned)__bfloat16_as_ushort(h1) << 16);
            l = (unsigned)__bfloat16_as_ushort(__float2bfloat16_rn(l0)) |
                ((unsigned)__bfloat16_as_ushort(__float2bfloat16_rn(l1)) << 16);
        }
        g_fwT2h[idx] = h; g_fwT2l[idx] = l;
    }
}

// ---------------------------------------------------------------------------
// Tensor 11x11 reflect conv, 121ch -> 121ch, as 121 tap-GEMMs via mma.sync.
// (unchanged from R11 — measured 22.2ms total with this design)
// ---------------------------------------------------------------------------
#define SPX 144
__global__ void __launch_bounds__(256) convT_kern(
    const float* __restrict__ in, const unsigned int* __restrict__ wh,
    const unsigned int* __restrict__ wl, const float* __restrict__ bias,
    float* __restrict__ out, float outscale)
{
    __shared__ uint2 s_bh[SPX * 4], s_bl[SPX * 4];
    const int x0 = blockIdx.x * 128, y = blockIdx.y, b = blockIdx.z;
    const int tid = threadIdx.x, w = tid >> 5, lane = tid & 31;
    const int ch = w & 1;        // co half
    const int pq = w >> 1;       // px quarter
    const int lr = lane >> 2, lc = lane & 3;

    float acc[4][4][4];
#pragma unroll
    for (int m = 0; m < 4; ++m)
#pragma unroll
        for (int n = 0; n < 4; ++n)
#pragma unroll
            for (int q = 0; q < 4; ++q) acc[m][n][q] = 0.f;

    const size_t inB = (size_t)b * 121 * NPIX;

    for (int cc = 0; cc < 8; ++cc) {
        for (int dy = 0; dy < 11; ++dy) {
            __syncthreads();
            const int gy = refl(y + dy - 5);
            for (int t = tid; t < 16 * 138; t += 256) {
                int ci = t / 138, px = t - ci * 138;
                int cig = cc * 16 + ci;
                float v = 0.f;
                if (cig < 121)
                    v = in[inB + (size_t)cig * NPIX + gy * HW + refl(x0 + px - 5)];
                unsigned hv = __float_as_uint(v) & 0xFFFF0000u;
                float lo = v - __uint_as_float(hv);
                unsigned short ls = __bfloat16_as_ushort(__float2bfloat16_rn(lo));
                int p = ci >> 1;
                int off = (px * 4 + (p & 3)) * 8 + ((p >> 2) << 2) + ((ci & 1) << 1);
                *(unsigned short*)((char*)s_bh + off) = (unsigned short)(hv >> 16);
                *(unsigned short*)((char*)s_bl + off) = ls;
            }
            __syncthreads();
#pragma unroll 1
            for (int dx = 0; dx < 11; ++dx) {
                const int tap = dy * 11 + dx;
                uint4 ah[4], al[4];
#pragma unroll
                for (int m = 0; m < 4; ++m) {
                    size_t o = (((size_t)(tap * 8 + cc) * 8 + (ch * 4 + m)) << 7) + lane * 4;
                    ah[m] = *(const uint4*)(wh + o);
                    al[m] = *(const uint4*)(wl + o);
                }
                uint2 bh[4], bl[4];
#pragma unroll
                for (int n = 0; n < 4; ++n) {
                    int px = pq * 32 + n * 8 + lr + dx;
                    bh[n] = s_bh[px * 4 + lc];
                    bl[n] = s_bl[px * 4 + lc];
                }
#pragma unroll
                for (int m = 0; m < 4; ++m)
#pragma unroll
                    for (int n = 0; n < 4; ++n)
                        mma_bf16(acc[m][n], ah[m], bh[n].x, bh[n].y);
#pragma unroll
                for (int m = 0; m < 4; ++m)
#pragma unroll
                    for (int n = 0; n < 4; ++n)
                        mma_bf16(acc[m][n], al[m], bh[n].x, bh[n].y);
#pragma unroll
                for (int m = 0; m < 4; ++m)
#pragma unroll
                    for (int n = 0; n < 4; ++n)
                        mma_bf16(acc[m][n], ah[m], bl[n].x, bl[n].y);
            }
        }
    }

    const size_t outB = (size_t)b * 121 * NPIX + (size_t)y * HW;
#pragma unroll
    for (int m = 0; m < 4; ++m) {
#pragma unroll
        for (int hh = 0; hh < 2; ++hh) {
            int co = (ch * 4 + m) * 16 + lr + hh * 8;
            if (co >= 121) continue;
            float bv = bias ? bias[co] : 0.f;
#pragma unroll
            for (int n = 0; n < 4; ++n) {
                int px = x0 + pq * 32 + n * 8 + lc * 2;
                float2 v;
                v.x = acc[m][n][hh * 2 + 0] * outscale + bv;
                v.y = acc[m][n][hh * 2 + 1] * outscale + bv;
                *(float2*)(out + outB + (size_t)co * NPIX + px) = v;
            }
        }
    }
}

// ---------------------------------------------------------------------------
// Dedicated 11x11 reflect conv, 121ch -> 1ch (final Wt). 32x32 tile.
// ---------------------------------------------------------------------------
__global__ void __launch_bounds__(256) convWt_kern(
    const float* __restrict__ in, const float* __restrict__ wbuf,
    float* __restrict__ out, float outscale)
{
    constexpr int IN = 42, STR = 43;
    __shared__ float s_in[IN * STR];
    __shared__ float s_w[128];
    const int b = blockIdx.z, by = blockIdx.y, bx = blockIdx.x;
    const int tid = threadIdx.x;
    const int ty = tid >> 4, tx = tid & 15;
    const int r0 = ty * 2, c0 = tx * 2;
    float a00 = 0.f, a01 = 0.f, a10 = 0.f, a11 = 0.f;
    const size_t inBase = (size_t)b * 121 * NPIX;
    for (int ci = 0; ci < 121; ++ci) {
        const float* ip = in + inBase + (size_t)ci * NPIX;
        for (int idx = tid; idx < IN * IN; idx += 256) {
            int row = idx / IN, col = idx - row * IN;
            s_in[row * STR + col] =
                ip[refl(by * 32 + row - 5) * HW + refl(bx * 32 + col - 5)];
        }
        if (tid < 121) s_w[tid] = wbuf[ci * 121 + tid];
        __syncthreads();
#pragma unroll 1
        for (int r = 0; r < 11; ++r) {
            const float* p0 = &s_in[(r0 + r) * STR + c0];
            const float* p1 = p0 + STR;
#pragma unroll
            for (int s = 0; s < 11; ++s) {
                float wv = s_w[r * 11 + s];
                a00 += wv * p0[s];  a01 += wv * p0[s + 1];
                a10 += wv * p1[s];  a11 += wv * p1[s + 1];
            }
        }
        __syncthreads();
    }
    const int oy = by * 32 + r0, ox = bx * 32 + c0;
    float* op = out + (size_t)b * NPIX;
    op[oy * HW + ox]           = a00 * outscale;
    op[oy * HW + ox + 1]       = a01 * outscale;
    op[(oy + 1) * HW + ox]     = a10 * outscale;
    op[(oy + 1) * HW + ox + 1] = a11 * outscale;
}

// ---------------------------------------------------------------------------
// Scalar KSxKS conv (FFMA2) — Wx1 (Cin=1) and 3x3 SE convs.
// ---------------------------------------------------------------------------
template<int KS, bool REFLECT, bool CLIP>
__global__ void __launch_bounds__(256) convK_kern(
    const float* __restrict__ in, const float* __restrict__ wbuf,
    const float* __restrict__ bias, const float* __restrict__ chscale,
    float* __restrict__ out, int Cin, int Cout, float outscale)
{
    constexpr int PAD = KS / 2;
    constexpr int IN  = 32 + KS - 1;
    constexpr int STR = IN + 1;
    constexpr int KK  = KS * KS;
    __shared__ __align__(16) float s_w8[KK * 8];
    __shared__ float s_in[IN * STR];

    const int nCoG = (Cout + 7) >> 3;
    const int b    = blockIdx.z / nCoG;
    const int cog  = blockIdx.z % nCoG;
    const int by = blockIdx.y, bx = blockIdx.x;
    const int tid = threadIdx.x;
    const int ty = tid >> 4, tx = tid & 15;
    const int r0 = ty * 2, c0 = tx * 2;

    unsigned long long acc2[4][4];
#pragma unroll
    for (int p = 0; p < 4; ++p)
#pragma unroll
        for (int q = 0; q < 4; ++q) acc2[p][q] = 0ull;

    const size_t inBase  = (size_t)b * Cin * NPIX;
    const int    co0     = cog * 8;
    const size_t wstride = (size_t)Cin * KK;

    for (int ci = 0; ci < Cin; ++ci) {
        const float* ip = in + inBase + (size_t)ci * NPIX;
        float sc = 1.f;
        if (chscale) sc = chscale[b * Cin + ci];
        for (int idx = tid; idx < IN * IN; idx += 256) {
            int row = idx / IN, col = idx - row * IN;
            int gy = by * 32 + row - PAD;
            int gx = bx * 32 + col - PAD;
            float v;
            if (REFLECT) v = ip[refl(gy) * HW + refl(gx)];
            else v = (gy >= 0 && gy < HW && gx >= 0 && gx < HW) ? ip[gy * HW + gx] : 0.f;
            s_in[row * STR + col] = v * sc;
        }
        {
            const float* wci = wbuf + (size_t)ci * KK;
            for (int t = tid; t < KK * 8; t += 256) {
                int tap = t >> 3, j = t & 7;
                int co  = co0 + j;
                int cosafe = (co < Cout) ? co : (Cout - 1);
                float wv = wci[(size_t)cosafe * wstride + tap];
                s_w8[t] = (co < Cout) ? wv : 0.f;
            }
        }
        __syncthreads();
#pragma unroll 1
        for (int r = 0; r < KS; ++r) {
            const float* p0 = &s_in[(r0 + r) * STR + c0];
            const float* p1 = p0 + STR;
#pragma unroll
            for (int s = 0; s < KS; ++s) {
                const unsigned long long* wq =
                    (const unsigned long long*)&s_w8[(r * KS + s) * 8];
                unsigned long long w01 = wq[0], w23 = wq[1];
                unsigned long long w45 = wq[2], w67 = wq[3];
                unsigned long long v00 = pack2(p0[s], p0[s]);
                unsigned long long v01 = pack2(p0[s + 1], p0[s + 1]);
                unsigned long long v10 = pack2(p1[s], p1[s]);
                unsigned long long v11 = pack2(p1[s + 1], p1[s + 1]);
                fma2(acc2[0][0], w01, v00); fma2(acc2[0][1], w23, v00);
                fma2(acc2[0][2], w45, v00); fma2(acc2[0][3], w67, v00);
                fma2(acc2[1][0], w01, v01); fma2(acc2[1][1], w23, v01);
                fma2(acc2[1][2], w45, v01); fma2(acc2[1][3], w67, v01);
                fma2(acc2[2][0], w01, v10); fma2(acc2[2][1], w23, v10);
                fma2(acc2[2][2], w45, v10); fma2(acc2[2][3], w67, v10);
                fma2(acc2[3][0], w01, v11); fma2(acc2[3][1], w23, v11);
                fma2(acc2[3][2], w45, v11); fma2(acc2[3][3], w67, v11);
            }
        }
        __syncthreads();
    }

    float acc[4][8];
#pragma unroll
    for (int p = 0; p < 4; ++p)
#pragma unroll
        for (int q = 0; q < 4; ++q)
            unpack2(acc2[p][q], acc[p][2 * q], acc[p][2 * q + 1]);

    const int oy = by * 32 + r0, ox = bx * 32 + c0;
    const size_t outBase = (size_t)b * Cout * NPIX;
#pragma unroll
    for (int j = 0; j < 8; ++j) {
        int co = co0 + j;
        if (co >= Cout) break;
        float bv = bias ? bias[co] : 0.f;
        float* op = out + outBase + (size_t)co * NPIX;
        float r00 = acc[0][j] * outscale + bv;
        float r01 = acc[1][j] * outscale + bv;
        float r10 = acc[2][j] * outscale + bv;
        float r11 = acc[3][j] * outscale + bv;
        if (CLIP) {
            r00 = fminf(fmaxf(r00, 0.f), 10.f);
            r01 = fminf(fmaxf(r01, 0.f), 10.f);
            r10 = fminf(fmaxf(r10, 0.f), 10.f);
            r11 = fminf(fmaxf(r11, 0.f), 10.f);
        }
        op[oy * HW + ox]           = r00;
        op[oy * HW + ox + 1]       = r01;
        op[(oy + 1) * HW + ox]     = r10;
        op[(oy + 1) * HW + ox + 1] = r11;
    }
}

template<bool RESID>
__global__ void __launch_bounds__(256) conv1x1_kern(
    const float* __restrict__ x, const float* __restrict__ w,
    const float* __restrict__ resid, float* __restrict__ out,
    int Cin, int Cout)
{
    __shared__ float4 s_w[244 * 4];
    const int b   = blockIdx.z;
    const int co0 = blockIdx.y * 16;
    const int px  = blockIdx.x * 256 + threadIdx.x;
    for (int t = threadIdx.x; t < Cin * 4; t += 256) {
        int ci = t >> 2, g = t & 3;
        int co = co0 + g * 4;
        float4 v;
        v.x = (co + 0 < Cout) ? w[(size_t)(co + 0) * Cin + ci] : 0.f;
        v.y = (co + 1 < Cout) ? w[(size_t)(co + 1) * Cin + ci] : 0.f;
        v.z = (co + 2 < Cout) ? w[(size_t)(co + 2) * Cin + ci] : 0.f;
        v.w = (co + 3 < Cout) ? w[(size_t)(co + 3) * Cin + ci] : 0.f;
        s_w[t] = v;
    }
    __syncthreads();
    float acc[16];
#pragma unroll
    for (int j = 0; j < 16; ++j) acc[j] = 0.f;
    const float* xp = x + (size_t)b * Cin * NPIX + px;
#pragma unroll 2
    for (int ci = 0; ci < Cin; ++ci) {
        float xv = xp[(size_t)ci * NPIX];
#pragma unroll
        for (int g = 0; g < 4; ++g) {
            float4 w4 = s_w[ci * 4 + g];
            acc[g * 4 + 0] += w4.x * xv;
            acc[g * 4 + 1] += w4.y * xv;
            acc[g * 4 + 2] += w4.z * xv;
            acc[g * 4 + 3] += w4.w * xv;
        }
    }
    const size_t ob = (size_t)b * Cout * NPIX + px;
#pragma unroll
    for (int j = 0; j < 16; ++j) {
        int co = co0 + j;
        if (co < Cout) {
            float v = acc[j];
            if (RESID) v += resid[ob + (size_t)co * NPIX];
            out[ob + (size_t)co * NPIX] = v;
        }
    }
}

__global__ void ln_cat_kern(const float* __restrict__ in0, const float* __restrict__ wx,
                            const float* __restrict__ gw, const float* __restrict__ gb)
{
    int t = blockIdx.x * 256 + threadIdx.x;
    if (t >= 2 * NPIX) return;
    int b = t >> 16, p = t & (NPIX - 1);
    float x0 = in0[t];
    const float* wp = wx + (size_t)b * 121 * NPIX + p;
    float sum = x0, ss = x0 * x0;
    for (int c = 0; c < 121; ++c) {
        float v = wp[(size_t)c * NPIX];
        sum += v; ss += v * v;
    }
    float mu  = sum * (1.f / 122.f);
    float var = ss * (1.f / 122.f) - mu * mu;
    float rs  = rsqrtf(var + 1e-5f);
    size_t base = (size_t)b * 122 * NPIX + p;
    g_cat[base] = x0;
    g_ln[base]  = (x0 - mu) * rs * gw[0] + gb[0];
    for (int c = 0; c < 121; ++c) {
        float v = wp[(size_t)c * NPIX];
        g_cat[base + (size_t)(c + 1) * NPIX] = v;
        g_ln[base + (size_t)(c + 1) * NPIX]  = (v - mu) * rs * gw[c + 1] + gb[c + 1];
    }
}

__global__ void dwconv_kern(const float* __restrict__ w)
{
    int c = blockIdx.y, b = blockIdx.z;
    int p = blockIdx.x * 256 + threadIdx.x;
    int y = p >> 8, x = p & 255;
    const float* ip = g_h + ((size_t)(b * 732 + c)) * NPIX;
    float wv[9];
#pragma unroll
    for (int i = 0; i < 9; ++i) wv[i] = w[c * 9 + i];
    float acc = 0.f;
#pragma unroll
    for (int dy = 0; dy < 3; ++dy) {
        int yy = y + dy - 1;
        if (yy < 0 || yy > 255) continue;
#pragma unroll
        for (int dx = 0; dx < 3; ++dx) {
            int xx = x + dx - 1;
            if (xx < 0 || xx > 255) continue;
            acc += wv[dy * 3 + dx] * ip[yy * HW + xx];
        }
    }
    g_h2[((size_t)(b * 732 + c)) * NPIX + p] = acc;
}

__global__ void circ8_kern()
{
    __shared__ float sq[4][64], sk[4][64];
    int pt = threadIdx.x >> 6;
    int t  = threadIdx.x & 63;
    long long pid = (long long)blockIdx.x * 4 + pt;
    int pb = (int)(pid & 1023);
    int bc = (int)(pid >> 10);
    int b = bc / 244, c = bc % 244;
    int py = pb >> 5, px = pb & 31;
    int row = t >> 3, col = t & 7;
    size_t qbase = ((size_t)(b * 732 + c)) * NPIX + (py * 8 + row) * HW + px * 8 + col;
    sq[pt][t] = g_h2[qbase];
    sk[pt][t] = g_h2[qbase + (size_t)244 * NPIX];
    __syncthreads();
    int m = row, n = col;
    float acc = 0.f;
#pragma unroll
    for (int i = 0; i < 8; ++i) {
        int km = (m - i) & 7;
#pragma unroll
        for (int j = 0; j < 8; ++j)
            acc += sq[pt][i * 8 + j] * sk[pt][km * 8 + ((n - j) & 7)];
    }
    g_h[((size_t)(b * 244 + c)) * NPIX + (py * 8 + m) * HW + px * 8 + n] = acc;
}

__global__ void ln2_mul_kern(const float* __restrict__ fnw, const float* __restrict__ fnb)
{
    int t = blockIdx.x * 256 + threadIdx.x;
    if (t >= 2 * NPIX) return;
    int b = t >> 16, p = t & (NPIX - 1);
    float* op = g_h + (size_t)b * 244 * NPIX + p;
    const float* vp = g_h2 + ((size_t)b * 732 + 488) * NPIX + p;
    float sum = 0.f, ss = 0.f;
    for (int c = 0; c < 244; ++c) {
        float v = op[(size_t)c * NPIX];
        sum += v; ss += v * v;
    }
    float mu  = sum * (1.f / 244.f);
    float var = ss * (1.f / 244.f) - mu * mu;
    float rs  = rsqrtf(var + 1e-5f);
    for (int c = 0; c < 244; ++c) {
        float v = op[(size_t)c * NPIX];
        float nrm = (v - mu) * rs * fnw[c] + fnb[c];
        op[(size_t)c * NPIX] = vp[(size_t)c * NPIX] * nrm;
    }
}

__global__ void se_mean_kern()
{
    int c = blockIdx.x, b = blockIdx.y;
    const float* p = g_out + ((size_t)b * 122 + c) * NPIX;
    float s = 0.f;
    for (int i = threadIdx.x; i < NPIX; i += 256) s += p[i];
    __shared__ float red[256];
    red[threadIdx.x] = s;
    __syncthreads();
    for (int k = 128; k > 0; k >>= 1) {
        if (threadIdx.x < k) red[threadIdx.x] += red[threadIdx.x + k];
        __syncthreads();
    }
    if (threadIdx.x == 0) g_sey[b * 122 + c] = red[0] * (1.f / (float)NPIX);
}

__global__ void se_mlp_kern(const float* __restrict__ f1, const float* __restrict__ f2)
{
    int b = blockIdx.x;
    __shared__ float ym[122];
    __shared__ float y7[7];
    if (threadIdx.x < 122) ym[threadIdx.x] = g_sey[b * 122 + threadIdx.x];
    __syncthreads();
    if (threadIdx.x < 7) {
        float a = 0.f;
        for (int c = 0; c < 122; ++c) a += f1[threadIdx.x * 122 + c] * ym[c];
        y7[threadIdx.x] = fmaxf(a, 0.f);
    }
    __syncthreads();
    if (threadIdx.x < 122) {
        float a = 0.f;
#pragma unroll
        for (int j = 0; j < 7; ++j) a += f2[threadIdx.x * 7 + j] * y7[j];
        g_se[b * 122 + threadIdx.x] = 1.f / (1.f + expf(-a));
    }
}

__global__ void soft_kern(const float* __restrict__ wx, const float* __restrict__ cth,
                          const float* __restrict__ sigma, float* __restrict__ z)
{
    size_t i = (size_t)blockIdx.x * 256 + threadIdx.x;
    if (i >= (size_t)2 * 121 * NPIX) return;
    int b = (int)(i / ((size_t)121 * NPIX));
    int p = (int)(i & (NPIX - 1));
    float t = cth[i] * sigma[b * NPIX + p];
    float x = wx[i];
    float r = 0.f;
    if (x > t) r = x - t;
    else if (x < -t) r = x + t;
    z[i] = r;
}

__global__ void init_out_kern(const float* __restrict__ w1, float* __restrict__ out)
{
    int i = blockIdx.x * 256 + threadIdx.x;
    if (i < 14641) out[131072 + i] = w1[i];
    if (i == 0) g_loss = 0.0;
}

// loss = sum((WTW2 - Wx1)^2), WTW2 in g_tC
__global__ void loss_kern()
{
    const size_t N = (size_t)2 * 121 * NPIX;
    double s = 0.0;
    for (size_t i = (size_t)blockIdx.x * 256 + threadIdx.x; i < N; i += (size_t)gridDim.x * 256) {
        float d = g_tC[i] - g_Wx1[i];
        s += (double)d * (double)d;
    }
    __shared__ double red[256];
    red[threadIdx.x] = s;
    __syncthreads();
    for (int k = 128; k > 0; k >>= 1) {
        if (threadIdx.x < k) red[threadIdx.x] += red[threadIdx.x + k];
        __syncthreads();
    }
    if (threadIdx.x == 0) atomicAdd(&g_loss, red[0]);
}

__global__ void loss_fin_kern(float* __restrict__ out)
{
    if (threadIdx.x == 0 && blockIdx.x == 0) out[145713] = (float)g_loss;
}

extern "C" void kernel_launch(void* const* d_in, const int* in_sizes, int n_in,
                              void* d_out, int out_size)
{
    const float* input = (const float*)d_in[0];
    const float* sigma = (const float*)d_in[1];
    const float* w1    = (const float*)d_in[2];
    const float* b1    = (const float*)d_in[3];
    const float* w2    = (const float*)d_in[4];
    const float* b2    = (const float*)d_in[5];
    const float* n1w   = (const float*)d_in[6];
    const float* n1b   = (const float*)d_in[7];
    const float* thw   = (const float*)d_in[8];
    const float* tdw   = (const float*)d_in[9];
    const float* fnw   = (const float*)d_in[10];
    const float* fnb   = (const float*)d_in[11];
    const float* pw    = (const float*)d_in[12];
    const float* s1a   = (const float*)d_in[13];
    const float* s1b   = (const float*)d_in[14];
    const float* s2a   = (const float*)d_in[15];
    const float* s2b   = (const float*)d_in[16];
    const float* c1w   = (const float*)d_in[17];
    const float* c1b   = (const float*)d_in[18];
    const float* c2w   = (const float*)d_in[19];
    const float* c2b   = (const float*)d_in[20];
    float* out = (float*)d_out;

    float *pWx1, *pWx2, *pZ, *pTA, *pTB, *pTC, *pLn, *pH, *pCat, *pOut, *pWT1, *pSe;
    unsigned int *pF2h, *pF2l, *pFTh, *pFTl;
    cudaGetSymbolAddress((void**)&pWx1, g_Wx1);
    cudaGetSymbolAddress((void**)&pWx2, g_Wx2);
    cudaGetSymbolAddress((void**)&pZ,   g_z);
    cudaGetSymbolAddress((void**)&pTA,  g_tA);
    cudaGetSymbolAddress((void**)&pTB,  g_tB);
    cudaGetSymbolAddress((void**)&pTC,  g_tC);
    cudaGetSymbolAddress((void**)&pLn,  g_ln);
    cudaGetSymbolAddress((void**)&pH,   g_h);
    cudaGetSymbolAddress((void**)&pCat, g_cat);
    cudaGetSymbolAddress((void**)&pOut, g_out);
    cudaGetSymbolAddress((void**)&pWT1, g_wT1);
    cudaGetSymbolAddress((void**)&pSe,  g_se);
    cudaGetSymbolAddress((void**)&pF2h, g_fw2h);
    cudaGetSymbolAddress((void**)&pF2l, g_fw2l);
    cudaGetSymbolAddress((void**)&pFTh, g_fwT2h);
    cudaGetSymbolAddress((void**)&pFTl, g_fwT2l);

    const float inv121 = 1.f / 121.f;
    const dim3 blk(256);
    const dim3 gridC121(8, 8, 2 * 16);
    const dim3 gridT(2, 256, 2);
    const dim3 gridW(8, 8, 2);
    const dim3 gridPix((2 * NPIX) / 256);

    // launches 0-3
    prep_w_kern<<<58, blk>>>(w1);
    prep_frag_kern<<<2048, blk>>>(w2);
    init_out_kern<<<58, blk>>>(w1, out);
    convK_kern<11, true, false><<<gridC121, blk>>>(input, w1, b1, nullptr, pWx1, 1, 121, 1.f);

    // W2loss chain — depends only on Wx1; hoisted so ncu (-s 5) captures convT.
    // launch 4: temp = convT(Wx1, w2)+b2 ; launch 5: WTW2 = convT(temp, wT2)/121
    convT_kern<<<gridT, blk>>>(pWx1, pF2h, pF2l, b2, pTB, 1.f);
    convT_kern<<<gridT, blk>>>(pTB, pFTh, pFTl, nullptr, pTC, inv121);
    loss_kern<<<1024, blk>>>();
    loss_fin_kern<<<1, 32>>>(out);

    for (int pass = 0; pass < 2; ++pass) {
        const float* wx  = (pass == 0) ? pWx1 : pWx2;
        const float* sea = (pass == 0) ? s1a : s2a;
        const float* seb = (pass == 0) ? s1b : s2b;
        const float* cw  = (pass == 0) ? c1w : c2w;
        const float* cb  = (pass == 0) ? c1b : c2b;

        ln_cat_kern<<<gridPix, blk>>>(input, wx, n1w, n1b);
        conv1x1_kern<false><<<dim3(256, 46, 2), blk>>>(pLn, thw, nullptr, pH, 122, 732);
        dwconv_kern<<<dim3(256, 732, 2), blk>>>(tdw);
        circ8_kern<<<124928, blk>>>();
        ln2_mul_kern<<<gridPix, blk>>>(fnw, fnb);
        conv1x1_kern<true><<<dim3(256, 8, 2), blk>>>(pH, pw, pCat, pOut, 244, 122);

        se_mean_kern<<<dim3(122, 2), blk>>>();
        se_mlp_kern<<<2, 128>>>(sea, seb);
        convK_kern<3, false, true><<<gridC121, blk>>>(pOut, cw, cb, pSe, pTA, 122, 121, 1.f);
        soft_kern<<<61952, blk>>>(wx, pTA, sigma, pZ);

        if (pass == 0)
            convT_kern<<<gridT, blk>>>(pZ, pF2h, pF2l, b2, pWx2, 1.f);
    }

    // Wt2 = convT(z2, wT2)/121 ; Wt = dedicated Cout=1 conv with wT1, /121
    convT_kern<<<gridT, blk>>>(pZ, pFTh, pFTl, nullptr, pTA, inv121);
    convWt_kern<<<gridW, blk>>>(pTA, pWT1, out, inv121);
}

// round 13
// speedup vs baseline: 2.3249x; 1.0151x over previous
#include <cuda_runtime.h>
#include <cuda_bf16.h>

#define NPIX 65536
#define HW 256
#define NFRAG (121*8*8*32*4)   // tap, cichunk, coatom, lane, word

__device__ float g_Wx1[2 * 121 * NPIX];
__device__ float g_Wx2[2 * 121 * NPIX];
__device__ float g_z  [2 * 121 * NPIX];
__device__ float g_tA [2 * 121 * NPIX];
__device__ float g_tB [2 * 121 * NPIX];
__device__ float g_tC [2 * 121 * NPIX];
__device__ float g_cat[2 * 122 * NPIX];
__device__ float g_ln [2 * 122 * NPIX];
__device__ float g_out[2 * 122 * NPIX];
__device__ float g_h  [2 * 732 * NPIX];
__device__ float g_h2 [2 * 732 * NPIX];
__device__ float g_wT1[121 * 121];
__device__ float g_sey[2 * 122];
__device__ float g_se [2 * 122];
__device__ double g_loss;
__device__ unsigned int g_fw2h[NFRAG], g_fw2l[NFRAG];
__device__ unsigned int g_fwT2h[NFRAG], g_fwT2l[NFRAG];

__device__ __forceinline__ int refl(int i) {
    i = (i < 0) ? -i : i;
    return (i < HW) ? i : (2 * HW - 2 - i);
}
__device__ __forceinline__ unsigned long long pack2(float lo, float hi) {
    unsigned long long r;
    asm("mov.b64 %0, {%1, %2};" : "=l"(r) : "f"(lo), "f"(hi));
    return r;
}
__device__ __forceinline__ void fma2(unsigned long long& a, unsigned long long w,
                                     unsigned long long v) {
    asm("fma.rn.f32x2 %0, %1, %2, %0;" : "+l"(a) : "l"(w), "l"(v));
}
__device__ __forceinline__ void unpack2(unsigned long long v, float& lo, float& hi) {
    asm("mov.b64 {%0, %1}, %2;" : "=f"(lo), "=f"(hi) : "l"(v));
}
__device__ __forceinline__ void mma_bf16(float* c, uint4 a, unsigned int b0, unsigned int b1) {
    asm volatile("mma.sync.aligned.m16n8k16.row.col.f32.bf16.bf16.f32 "
                 "{%0,%1,%2,%3},{%4,%5,%6,%7},{%8,%9},{%0,%1,%2,%3};"
                 : "+f"(c[0]), "+f"(c[1]), "+f"(c[2]), "+f"(c[3])
                 : "r"(a.x), "r"(a.y), "r"(a.z), "r"(a.w), "r"(b0), "r"(b1));
}

// wT1[ci][tap] = w1[ci][120-tap]
__global__ void prep_w_kern(const float* __restrict__ w1)
{
    int i = blockIdx.x * 256 + threadIdx.x;
    if (i < 121 * 121) {
        int ci = i / 121, tap = i % 121;
        g_wT1[ci * 121 + tap] = w1[ci * 121 + (120 - tap)];
    }
}

// Pre-fragment w2 and wT2 into mma A-fragments (hi/lo bf16 split).
// idx = (((tap*8+cc)*8+atom)*32+lane)*4+j ; word j: j&1 -> row+8, j>=2 -> k+8
__global__ void prep_frag_kern(const float* __restrict__ w2)
{
    for (int idx = blockIdx.x * 256 + threadIdx.x; idx < NFRAG; idx += gridDim.x * 256) {
        int j    = idx & 3;
        int lane = (idx >> 2) & 31;
        int atom = (idx >> 7) & 7;
        int cc   = (idx >> 10) & 7;
        int tap  = idx >> 13;
        int co = atom * 16 + (lane >> 2) + ((j & 1) ? 8 : 0);
        int k0 = (lane & 3) * 2 + ((j >= 2) ? 8 : 0);
        float a[2], t[2];
#pragma unroll
        for (int e = 0; e < 2; ++e) {
            int ci = cc * 16 + k0 + e;
            bool ok = (co < 121) && (ci < 121);
            a[e] = ok ? w2[((size_t)co * 121 + ci) * 121 + tap] : 0.f;
            t[e] = ok ? w2[((size_t)ci * 121 + co) * 121 + (120 - tap)] : 0.f;
        }
        unsigned int h, l;
        {
            __nv_bfloat16 h0 = __float2bfloat16_rn(a[0]), h1 = __float2bfloat16_rn(a[1]);
            float l0 = a[0] - __bfloat162float(h0), l1 = a[1] - __bfloat162float(h1);
            h = (unsigned)__bfloat16_as_ushort(h0) | ((unsigned)__bfloat16_as_ushort(h1) << 16);
            l = (unsigned)__bfloat16_as_ushort(__float2bfloat16_rn(l0)) |
                ((unsigned)__bfloat16_as_ushort(__float2bfloat16_rn(l1)) << 16);
        }
        g_fw2h[idx] = h; g_fw2l[idx] = l;
        {
            __nv_bfloat16 h0 = __float2bfloat16_rn(t[0]), h1 = __float2bfloat16_rn(t[1]);
            float l0 = t[0] - __bfloat162float(h0), l1 = t[1] - __bfloat162float(h1);
            h = (unsigned)__bfloat16_as_ushort(h0) | ((unsigned)__bfloat16_as_ushort(h1) << 16);
            l = (unsigned)__bfloat16_as_ushort(__float2bfloat16_rn(l0)) |
                ((unsigned)__bfloat16_as_ushort(__float2bfloat16_rn(l1)) << 16);
        }
        g_fwT2h[idx] = h; g_fwT2l[idx] = l;
    }
}

// ---------------------------------------------------------------------------
// Tensor 11x11 reflect conv, 121ch -> 121ch, as 121 tap-GEMMs via mma.sync.
// Warp remap vs R11: ch = w&3 (pair of co m-atoms), pq = w>>2 (px half, 8
// n-atoms). Weight-fragment LDG per warp per dx drops 16 -> 4 (redundancy
// 4 -> 2); B-frag LDS rises 8 -> 16 (cheaper pipe). Same mma sequence per
// output -> numerics bit-identical to R11/R12.
// ---------------------------------------------------------------------------
#define SPX 144
__global__ void __launch_bounds__(256) convT_kern(
    const float* __restrict__ in, const unsigned int* __restrict__ wh,
    const unsigned int* __restrict__ wl, const float* __restrict__ bias,
    float* __restrict__ out, float outscale)
{
    __shared__ uint2 s_bh[SPX * 4], s_bl[SPX * 4];
    const int x0 = blockIdx.x * 128, y = blockIdx.y, b = blockIdx.z;
    const int tid = threadIdx.x, w = tid >> 5, lane = tid & 31;
    const int ch = w & 3;        // co atom-pair: atoms {ch*2, ch*2+1}
    const int pq = w >> 2;       // px half: 8 n-atoms
    const int lr = lane >> 2, lc = lane & 3;

    float acc[2][8][4];
#pragma unroll
    for (int m = 0; m < 2; ++m)
#pragma unroll
        for (int n = 0; n < 8; ++n)
#pragma unroll
            for (int q = 0; q < 4; ++q) acc[m][n][q] = 0.f;

    const size_t inB = (size_t)b * 121 * NPIX;

    for (int cc = 0; cc < 8; ++cc) {
        for (int dy = 0; dy < 11; ++dy) {
            __syncthreads();
            const int gy = refl(y + dy - 5);
            for (int t = tid; t < 16 * 138; t += 256) {
                int ci = t / 138, px = t - ci * 138;
                int cig = cc * 16 + ci;
                float v = 0.f;
                if (cig < 121)
                    v = in[inB + (size_t)cig * NPIX + gy * HW + refl(x0 + px - 5)];
                unsigned hv = __float_as_uint(v) & 0xFFFF0000u;
                float lo = v - __uint_as_float(hv);
                unsigned short ls = __bfloat16_as_ushort(__float2bfloat16_rn(lo));
                int p = ci >> 1;
                int off = (px * 4 + (p & 3)) * 8 + ((p >> 2) << 2) + ((ci & 1) << 1);
                *(unsigned short*)((char*)s_bh + off) = (unsigned short)(hv >> 16);
                *(unsigned short*)((char*)s_bl + off) = ls;
            }
            __syncthreads();
#pragma unroll 1
            for (int dx = 0; dx < 11; ++dx) {
                const int tap = dy * 11 + dx;
                uint4 ah[2], al[2];
#pragma unroll
                for (int m = 0; m < 2; ++m) {
                    size_t o = (((size_t)(tap * 8 + cc) * 8 + (ch * 2 + m)) << 7) + lane * 4;
                    ah[m] = *(const uint4*)(wh + o);
                    al[m] = *(const uint4*)(wl + o);
                }
                uint2 bh[8], bl[8];
#pragma unroll
                for (int n = 0; n < 8; ++n) {
                    int px = pq * 64 + n * 8 + lr + dx;
                    bh[n] = s_bh[px * 4 + lc];
                    bl[n] = s_bl[px * 4 + lc];
                }
#pragma unroll
                for (int m = 0; m < 2; ++m)
#pragma unroll
                    for (int n = 0; n < 8; ++n)
                        mma_bf16(acc[m][n], ah[m], bh[n].x, bh[n].y);
#pragma unroll
                for (int m = 0; m < 2; ++m)
#pragma unroll
                    for (int n = 0; n < 8; ++n)
                        mma_bf16(acc[m][n], al[m], bh[n].x, bh[n].y);
#pragma unroll
                for (int m = 0; m < 2; ++m)
#pragma unroll
                    for (int n = 0; n < 8; ++n)
                        mma_bf16(acc[m][n], ah[m], bl[n].x, bl[n].y);
            }
        }
    }

    const size_t outB = (size_t)b * 121 * NPIX + (size_t)y * HW;
#pragma unroll
    for (int m = 0; m < 2; ++m) {
#pragma unroll
        for (int hh = 0; hh < 2; ++hh) {
            int co = (ch * 2 + m) * 16 + lr + hh * 8;
            if (co >= 121) continue;
            float bv = bias ? bias[co] : 0.f;
#pragma unroll
            for (int n = 0; n < 8; ++n) {
                int px = x0 + pq * 64 + n * 8 + lc * 2;
                float2 v;
                v.x = acc[m][n][hh * 2 + 0] * outscale + bv;
                v.y = acc[m][n][hh * 2 + 1] * outscale + bv;
                *(float2*)(out + outB + (size_t)co * NPIX + px) = v;
            }
        }
    }
}

// ---------------------------------------------------------------------------
// Dedicated 11x11 reflect conv, 121ch -> 1ch (final Wt). 32x32 tile.
// ---------------------------------------------------------------------------
__global__ void __launch_bounds__(256) convWt_kern(
    const float* __restrict__ in, const float* __restrict__ wbuf,
    float* __restrict__ out, float outscale)
{
    constexpr int IN = 42, STR = 43;
    __shared__ float s_in[IN * STR];
    __shared__ float s_w[128];
    const int b = blockIdx.z, by = blockIdx.y, bx = blockIdx.x;
    const int tid = threadIdx.x;
    const int ty = tid >> 4, tx = tid & 15;
    const int r0 = ty * 2, c0 = tx * 2;
    float a00 = 0.f, a01 = 0.f, a10 = 0.f, a11 = 0.f;
    const size_t inBase = (size_t)b * 121 * NPIX;
    for (int ci = 0; ci < 121; ++ci) {
        const float* ip = in + inBase + (size_t)ci * NPIX;
        for (int idx = tid; idx < IN * IN; idx += 256) {
            int row = idx / IN, col = idx - row * IN;
            s_in[row * STR + col] =
                ip[refl(by * 32 + row - 5) * HW + refl(bx * 32 + col - 5)];
        }
        if (tid < 121) s_w[tid] = wbuf[ci * 121 + tid];
        __syncthreads();
#pragma unroll 1
        for (int r = 0; r < 11; ++r) {
            const float* p0 = &s_in[(r0 + r) * STR + c0];
            const float* p1 = p0 + STR;
#pragma unroll
            for (int s = 0; s < 11; ++s) {
                float wv = s_w[r * 11 + s];
                a00 += wv * p0[s];  a01 += wv * p0[s + 1];
                a10 += wv * p1[s];  a11 += wv * p1[s + 1];
            }
        }
        __syncthreads();
    }
    const int oy = by * 32 + r0, ox = bx * 32 + c0;
    float* op = out + (size_t)b * NPIX;
    op[oy * HW + ox]           = a00 * outscale;
    op[oy * HW + ox + 1]       = a01 * outscale;
    op[(oy + 1) * HW + ox]     = a10 * outscale;
    op[(oy + 1) * HW + ox + 1] = a11 * outscale;
}

// ---------------------------------------------------------------------------
// Scalar KSxKS conv (FFMA2) — Wx1 (Cin=1) and 3x3 SE convs.
// ---------------------------------------------------------------------------
template<int KS, bool REFLECT, bool CLIP>
__global__ void __launch_bounds__(256) convK_kern(
    const float* __restrict__ in, const float* __restrict__ wbuf,
    const float* __restrict__ bias, const float* __restrict__ chscale,
    float* __restrict__ out, int Cin, int Cout, float outscale)
{
    constexpr int PAD = KS / 2;
    constexpr int IN  = 32 + KS - 1;
    constexpr int STR = IN + 1;
    constexpr int KK  = KS * KS;
    __shared__ __align__(16) float s_w8[KK * 8];
    __shared__ float s_in[IN * STR];

    const int nCoG = (Cout + 7) >> 3;
    const int b    = blockIdx.z / nCoG;
    const int cog  = blockIdx.z % nCoG;
    const int by = blockIdx.y, bx = blockIdx.x;
    const int tid = threadIdx.x;
    const int ty = tid >> 4, tx = tid & 15;
    const int r0 = ty * 2, c0 = tx * 2;

    unsigned long long acc2[4][4];
#pragma unroll
    for (int p = 0; p < 4; ++p)
#pragma unroll
        for (int q = 0; q < 4; ++q) acc2[p][q] = 0ull;

    const size_t inBase  = (size_t)b * Cin * NPIX;
    const int    co0     = cog * 8;
    const size_t wstride = (size_t)Cin * KK;

    for (int ci = 0; ci < Cin; ++ci) {
        const float* ip = in + inBase + (size_t)ci * NPIX;
        float sc = 1.f;
        if (chscale) sc = chscale[b * Cin + ci];
        for (int idx = tid; idx < IN * IN; idx += 256) {
            int row = idx / IN, col = idx - row * IN;
            int gy = by * 32 + row - PAD;
            int gx = bx * 32 + col - PAD;
            float v;
            if (REFLECT) v = ip[refl(gy) * HW + refl(gx)];
            else v = (gy >= 0 && gy < HW && gx >= 0 && gx < HW) ? ip[gy * HW + gx] : 0.f;
            s_in[row * STR + col] = v * sc;
        }
        {
            const float* wci = wbuf + (size_t)ci * KK;
            for (int t = tid; t < KK * 8; t += 256) {
                int tap = t >> 3, j = t & 7;
                int co  = co0 + j;
                int cosafe = (co < Cout) ? co : (Cout - 1);
                float wv = wci[(size_t)cosafe * wstride + tap];
                s_w8[t] = (co < Cout) ? wv : 0.f;
            }
        }
        __syncthreads();
#pragma unroll 1
        for (int r = 0; r < KS; ++r) {
            const float* p0 = &s_in[(r0 + r) * STR + c0];
            const float* p1 = p0 + STR;
#pragma unroll
            for (int s = 0; s < KS; ++s) {
                const unsigned long long* wq =
                    (const unsigned long long*)&s_w8[(r * KS + s) * 8];
                unsigned long long w01 = wq[0], w23 = wq[1];
                unsigned long long w45 = wq[2], w67 = wq[3];
                unsigned long long v00 = pack2(p0[s], p0[s]);
                unsigned long long v01 = pack2(p0[s + 1], p0[s + 1]);
                unsigned long long v10 = pack2(p1[s], p1[s]);
                unsigned long long v11 = pack2(p1[s + 1], p1[s + 1]);
                fma2(acc2[0][0], w01, v00); fma2(acc2[0][1], w23, v00);
                fma2(acc2[0][2], w45, v00); fma2(acc2[0][3], w67, v00);
                fma2(acc2[1][0], w01, v01); fma2(acc2[1][1], w23, v01);
                fma2(acc2[1][2], w45, v01); fma2(acc2[1][3], w67, v01);
                fma2(acc2[2][0], w01, v10); fma2(acc2[2][1], w23, v10);
                fma2(acc2[2][2], w45, v10); fma2(acc2[2][3], w67, v10);
                fma2(acc2[3][0], w01, v11); fma2(acc2[3][1], w23, v11);
                fma2(acc2[3][2], w45, v11); fma2(acc2[3][3], w67, v11);
            }
        }
        __syncthreads();
    }

    float acc[4][8];
#pragma unroll
    for (int p = 0; p < 4; ++p)
#pragma unroll
        for (int q = 0; q < 4; ++q)
            unpack2(acc2[p][q], acc[p][2 * q], acc[p][2 * q + 1]);

    const int oy = by * 32 + r0, ox = bx * 32 + c0;
    const size_t outBase = (size_t)b * Cout * NPIX;
#pragma unroll
    for (int j = 0; j < 8; ++j) {
        int co = co0 + j;
        if (co >= Cout) break;
        float bv = bias ? bias[co] : 0.f;
        float* op = out + outBase + (size_t)co * NPIX;
        float r00 = acc[0][j] * outscale + bv;
        float r01 = acc[1][j] * outscale + bv;
        float r10 = acc[2][j] * outscale + bv;
        float r11 = acc[3][j] * outscale + bv;
        if (CLIP) {
            r00 = fminf(fmaxf(r00, 0.f), 10.f);
            r01 = fminf(fmaxf(r01, 0.f), 10.f);
            r10 = fminf(fmaxf(r10, 0.f), 10.f);
            r11 = fminf(fmaxf(r11, 0.f), 10.f);
        }
        op[oy * HW + ox]           = r00;
        op[oy * HW + ox + 1]       = r01;
        op[(oy + 1) * HW + ox]     = r10;
        op[(oy + 1) * HW + ox + 1] = r11;
    }
}

template<bool RESID>
__global__ void __launch_bounds__(256) conv1x1_kern(
    const float* __restrict__ x, const float* __restrict__ w,
    const float* __restrict__ resid, float* __restrict__ out,
    int Cin, int Cout)
{
    __shared__ float4 s_w[244 * 4];
    const int b   = blockIdx.z;
    const int co0 = blockIdx.y * 16;
    const int px  = blockIdx.x * 256 + threadIdx.x;
    for (int t = threadIdx.x; t < Cin * 4; t += 256) {
        int ci = t >> 2, g = t & 3;
        int co = co0 + g * 4;
        float4 v;
        v.x = (co + 0 < Cout) ? w[(size_t)(co + 0) * Cin + ci] : 0.f;
        v.y = (co + 1 < Cout) ? w[(size_t)(co + 1) * Cin + ci] : 0.f;
        v.z = (co + 2 < Cout) ? w[(size_t)(co + 2) * Cin + ci] : 0.f;
        v.w = (co + 3 < Cout) ? w[(size_t)(co + 3) * Cin + ci] : 0.f;
        s_w[t] = v;
    }
    __syncthreads();
    float acc[16];
#pragma unroll
    for (int j = 0; j < 16; ++j) acc[j] = 0.f;
    const float* xp = x + (size_t)b * Cin * NPIX + px;
#pragma unroll 2
    for (int ci = 0; ci < Cin; ++ci) {
        float xv = xp[(size_t)ci * NPIX];
#pragma unroll
        for (int g = 0; g < 4; ++g) {
            float4 w4 = s_w[ci * 4 + g];
            acc[g * 4 + 0] += w4.x * xv;
            acc[g * 4 + 1] += w4.y * xv;
            acc[g * 4 + 2] += w4.z * xv;
            acc[g * 4 + 3] += w4.w * xv;
        }
    }
    const size_t ob = (size_t)b * Cout * NPIX + px;
#pragma unroll
    for (int j = 0; j < 16; ++j) {
        int co = co0 + j;
        if (co < Cout) {
            float v = acc[j];
            if (RESID) v += resid[ob + (size_t)co * NPIX];
            out[ob + (size_t)co * NPIX] = v;
        }
    }
}

__global__ void ln_cat_kern(const float* __restrict__ in0, const float* __restrict__ wx,
                            const float* __restrict__ gw, const float* __restrict__ gb)
{
    int t = blockIdx.x * 256 + threadIdx.x;
    if (t >= 2 * NPIX) return;
    int b = t >> 16, p = t & (NPIX - 1);
    float x0 = in0[t];
    const float* wp = wx + (size_t)b * 121 * NPIX + p;
    float sum = x0, ss = x0 * x0;
    for (int c = 0; c < 121; ++c) {
        float v = wp[(size_t)c * NPIX];
        sum += v; ss += v * v;
    }
    float mu  = sum * (1.f / 122.f);
    float var = ss * (1.f / 122.f) - mu * mu;
    float rs  = rsqrtf(var + 1e-5f);
    size_t base = (size_t)b * 122 * NPIX + p;
    g_cat[base] = x0;
    g_ln[base]  = (x0 - mu) * rs * gw[0] + gb[0];
    for (int c = 0; c < 121; ++c) {
        float v = wp[(size_t)c * NPIX];
        g_cat[base + (size_t)(c + 1) * NPIX] = v;
        g_ln[base + (size_t)(c + 1) * NPIX]  = (v - mu) * rs * gw[c + 1] + gb[c + 1];
    }
}

__global__ void dwconv_kern(const float* __restrict__ w)
{
    int c = blockIdx.y, b = blockIdx.z;
    int p = blockIdx.x * 256 + threadIdx.x;
    int y = p >> 8, x = p & 255;
    const float* ip = g_h + ((size_t)(b * 732 + c)) * NPIX;
    float wv[9];
#pragma unroll
    for (int i = 0; i < 9; ++i) wv[i] = w[c * 9 + i];
    float acc = 0.f;
#pragma unroll
    for (int dy = 0; dy < 3; ++dy) {
        int yy = y + dy - 1;
        if (yy < 0 || yy > 255) continue;
#pragma unroll
        for (int dx = 0; dx < 3; ++dx) {
            int xx = x + dx - 1;
            if (xx < 0 || xx > 255) continue;
            acc += wv[dy * 3 + dx] * ip[yy * HW + xx];
        }
    }
    g_h2[((size_t)(b * 732 + c)) * NPIX + p] = acc;
}

__global__ void circ8_kern()
{
    __shared__ float sq[4][64], sk[4][64];
    int pt = threadIdx.x >> 6;
    int t  = threadIdx.x & 63;
    long long pid = (long long)blockIdx.x * 4 + pt;
    int pb = (int)(pid & 1023);
    int bc = (int)(pid >> 10);
    int b = bc / 244, c = bc % 244;
    int py = pb >> 5, px = pb & 31;
    int row = t >> 3, col = t & 7;
    size_t qbase = ((size_t)(b * 732 + c)) * NPIX + (py * 8 + row) * HW + px * 8 + col;
    sq[pt][t] = g_h2[qbase];
    sk[pt][t] = g_h2[qbase + (size_t)244 * NPIX];
    __syncthreads();
    int m = row, n = col;
    float acc = 0.f;
#pragma unroll
    for (int i = 0; i < 8; ++i) {
        int km = (m - i) & 7;
#pragma unroll
        for (int j = 0; j < 8; ++j)
            acc += sq[pt][i * 8 + j] * sk[pt][km * 8 + ((n - j) & 7)];
    }
    g_h[((size_t)(b * 244 + c)) * NPIX + (py * 8 + m) * HW + px * 8 + n] = acc;
}

__global__ void ln2_mul_kern(const float* __restrict__ fnw, const float* __restrict__ fnb)
{
    int t = blockIdx.x * 256 + threadIdx.x;
    if (t >= 2 * NPIX) return;
    int b = t >> 16, p = t & (NPIX - 1);
    float* op = g_h + (size_t)b * 244 * NPIX + p;
    const float* vp = g_h2 + ((size_t)b * 732 + 488) * NPIX + p;
    float sum = 0.f, ss = 0.f;
    for (int c = 0; c < 244; ++c) {
        float v = op[(size_t)c * NPIX];
        sum += v; ss += v * v;
    }
    float mu  = sum * (1.f / 244.f);
    float var = ss * (1.f / 244.f) - mu * mu;
    float rs  = rsqrtf(var + 1e-5f);
    for (int c = 0; c < 244; ++c) {
        float v = op[(size_t)c * NPIX];
        float nrm = (v - mu) * rs * fnw[c] + fnb[c];
        op[(size_t)c * NPIX] = vp[(size_t)c * NPIX] * nrm;
    }
}

__global__ void se_mean_kern()
{
    int c = blockIdx.x, b = blockIdx.y;
    const float* p = g_out + ((size_t)b * 122 + c) * NPIX;
    float s = 0.f;
    for (int i = threadIdx.x; i < NPIX; i += 256) s += p[i];
    __shared__ float red[256];
    red[threadIdx.x] = s;
    __syncthreads();
    for (int k = 128; k > 0; k >>= 1) {
        if (threadIdx.x < k) red[threadIdx.x] += red[threadIdx.x + k];
        __syncthreads();
    }
    if (threadIdx.x == 0) g_sey[b * 122 + c] = red[0] * (1.f / (float)NPIX);
}

__global__ void se_mlp_kern(const float* __restrict__ f1, const float* __restrict__ f2)
{
    int b = blockIdx.x;
    __shared__ float ym[122];
    __shared__ float y7[7];
    if (threadIdx.x < 122) ym[threadIdx.x] = g_sey[b * 122 + threadIdx.x];
    __syncthreads();
    if (threadIdx.x < 7) {
        float a = 0.f;
        for (int c = 0; c < 122; ++c) a += f1[threadIdx.x * 122 + c] * ym[c];
        y7[threadIdx.x] = fmaxf(a, 0.f);
    }
    __syncthreads();
    if (threadIdx.x < 122) {
        float a = 0.f;
#pragma unroll
        for (int j = 0; j < 7; ++j) a += f2[threadIdx.x * 7 + j] * y7[j];
        g_se[b * 122 + threadIdx.x] = 1.f / (1.f + expf(-a));
    }
}

__global__ void soft_kern(const float* __restrict__ wx, const float* __restrict__ cth,
                          const float* __restrict__ sigma, float* __restrict__ z)
{
    size_t i = (size_t)blockIdx.x * 256 + threadIdx.x;
    if (i >= (size_t)2 * 121 * NPIX) return;
    int b = (int)(i / ((size_t)121 * NPIX));
    int p = (int)(i & (NPIX - 1));
    float t = cth[i] * sigma[b * NPIX + p];
    float x = wx[i];
    float r = 0.f;
    if (x > t) r = x - t;
    else if (x < -t) r = x + t;
    z[i] = r;
}

__global__ void init_out_kern(const float* __restrict__ w1, float* __restrict__ out)
{
    int i = blockIdx.x * 256 + threadIdx.x;
    if (i < 14641) out[131072 + i] = w1[i];
    if (i == 0) g_loss = 0.0;
}

// loss = sum((WTW2 - Wx1)^2), WTW2 in g_tC
__global__ void loss_kern()
{
    const size_t N = (size_t)2 * 121 * NPIX;
    double s = 0.0;
    for (size_t i = (size_t)blockIdx.x * 256 + threadIdx.x; i < N; i += (size_t)gridDim.x * 256) {
        float d = g_tC[i] - g_Wx1[i];
        s += (double)d * (double)d;
    }
    __shared__ double red[256];
    red[threadIdx.x] = s;
    __syncthreads();
    for (int k = 128; k > 0; k >>= 1) {
        if (threadIdx.x < k) red[threadIdx.x] += red[threadIdx.x + k];
        __syncthreads();
    }
    if (threadIdx.x == 0) atomicAdd(&g_loss, red[0]);
}

__global__ void loss_fin_kern(float* __restrict__ out)
{
    if (threadIdx.x == 0 && blockIdx.x == 0) out[145713] = (float)g_loss;
}

extern "C" void kernel_launch(void* const* d_in, const int* in_sizes, int n_in,
                              void* d_out, int out_size)
{
    const float* input = (const float*)d_in[0];
    const float* sigma = (const float*)d_in[1];
    const float* w1    = (const float*)d_in[2];
    const float* b1    = (const float*)d_in[3];
    const float* w2    = (const float*)d_in[4];
    const float* b2    = (const float*)d_in[5];
    const float* n1w   = (const float*)d_in[6];
    const float* n1b   = (const float*)d_in[7];
    const float* thw   = (const float*)d_in[8];
    const float* tdw   = (const float*)d_in[9];
    const float* fnw   = (const float*)d_in[10];
    const float* fnb   = (const float*)d_in[11];
    const float* pw    = (const float*)d_in[12];
    const float* s1a   = (const float*)d_in[13];
    const float* s1b   = (const float*)d_in[14];
    const float* s2a   = (const float*)d_in[15];
    const float* s2b   = (const float*)d_in[16];
    const float* c1w   = (const float*)d_in[17];
    const float* c1b   = (const float*)d_in[18];
    const float* c2w   = (const float*)d_in[19];
    const float* c2b   = (const float*)d_in[20];
    float* out = (float*)d_out;

    float *pWx1, *pWx2, *pZ, *pTA, *pTB, *pTC, *pLn, *pH, *pCat, *pOut, *pWT1, *pSe;
    unsigned int *pF2h, *pF2l, *pFTh, *pFTl;
    cudaGetSymbolAddress((void**)&pWx1, g_Wx1);
    cudaGetSymbolAddress((void**)&pWx2, g_Wx2);
    cudaGetSymbolAddress((void**)&pZ,   g_z);
    cudaGetSymbolAddress((void**)&pTA,  g_tA);
    cudaGetSymbolAddress((void**)&pTB,  g_tB);
    cudaGetSymbolAddress((void**)&pTC,  g_tC);
    cudaGetSymbolAddress((void**)&pLn,  g_ln);
    cudaGetSymbolAddress((void**)&pH,   g_h);
    cudaGetSymbolAddress((void**)&pCat, g_cat);
    cudaGetSymbolAddress((void**)&pOut, g_out);
    cudaGetSymbolAddress((void**)&pWT1, g_wT1);
    cudaGetSymbolAddress((void**)&pSe,  g_se);
    cudaGetSymbolAddress((void**)&pF2h, g_fw2h);
    cudaGetSymbolAddress((void**)&pF2l, g_fw2l);
    cudaGetSymbolAddress((void**)&pFTh, g_fwT2h);
    cudaGetSymbolAddress((void**)&pFTl, g_fwT2l);

    const float inv121 = 1.f / 121.f;
    const dim3 blk(256);
    const dim3 gridC121(8, 8, 2 * 16);
    const dim3 gridT(2, 256, 2);
    const dim3 gridW(8, 8, 2);
    const dim3 gridPix((2 * NPIX) / 256);

    prep_w_kern<<<58, blk>>>(w1);
    prep_frag_kern<<<2048, blk>>>(w2);
    init_out_kern<<<58, blk>>>(w1, out);
    convK_kern<11, true, false><<<gridC121, blk>>>(input, w1, b1, nullptr, pWx1, 1, 121, 1.f);

    // W2loss chain (depends only on Wx1)
    convT_kern<<<gridT, blk>>>(pWx1, pF2h, pF2l, b2, pTB, 1.f);
    convT_kern<<<gridT, blk>>>(pTB, pFTh, pFTl, nullptr, pTC, inv121);
    loss_kern<<<1024, blk>>>();
    loss_fin_kern<<<1, 32>>>(out);

    for (int pass = 0; pass < 2; ++pass) {
        const float* wx  = (pass == 0) ? pWx1 : pWx2;
        const float* sea = (pass == 0) ? s1a : s2a;
        const float* seb = (pass == 0) ? s1b : s2b;
        const float* cw  = (pass == 0) ? c1w : c2w;
        const float* cb  = (pass == 0) ? c1b : c2b;

        ln_cat_kern<<<gridPix, blk>>>(input, wx, n1w, n1b);
        conv1x1_kern<false><<<dim3(256, 46, 2), blk>>>(pLn, thw, nullptr, pH, 122, 732);
        dwconv_kern<<<dim3(256, 732, 2), blk>>>(tdw);
        circ8_kern<<<124928, blk>>>();
        ln2_mul_kern<<<gridPix, blk>>>(fnw, fnb);
        conv1x1_kern<true><<<dim3(256, 8, 2), blk>>>(pH, pw, pCat, pOut, 244, 122);

        se_mean_kern<<<dim3(122, 2), blk>>>();
        se_mlp_kern<<<2, 128>>>(sea, seb);
        convK_kern<3, false, true><<<gridC121, blk>>>(pOut, cw, cb, pSe, pTA, 122, 121, 1.f);
        soft_kern<<<61952, blk>>>(wx, pTA, sigma, pZ);

        if (pass == 0)
            convT_kern<<<gridT, blk>>>(pZ, pF2h, pF2l, b2, pWx2, 1.f);
    }

    // Wt2 = convT(z2, wT2)/121 ; Wt = dedicated Cout=1 conv with wT1, /121
    convT_kern<<<gridT, blk>>>(pZ, pFTh, pFTl, nullptr, pTA, inv121);
    convWt_kern<<<gridW, blk>>>(pTA, pWT1, out, inv121);
}